// round 1
// baseline (speedup 1.0000x reference)
#include <cuda_runtime.h>
#include <math.h>

#define NTOK 2048
#define HD   2048
#define ID   7168
#define NE   8
#define NR   64
#define SCALE 0.25f

// ---------------- scratch (__device__ globals; no allocation) ----------------
__device__ float g_basegate[(size_t)NTOK * ID];
__device__ float g_baseup  [(size_t)NTOK * ID];
__device__ float g_hid     [2 * (size_t)NTOK * ID];
__device__ float g_hmix    [(size_t)NTOK * ID];
__device__ float g_tg      [NE * NTOK * NR];
__device__ float g_tu      [NE * NTOK * NR];
__device__ float g_corr    [2 * NTOK * NR];
__device__ float g_cvec    [NTOK * NE * NR];
__device__ float g_dball   [HD * NE * NR];
__device__ int   g_eids    [2 * NTOK];
__device__ float g_wts     [2 * NTOK];
__device__ int   g_cnt     [NE];
__device__ int   g_list    [NE * 2 * NTOK];

// ---------------- small kernels ----------------
__global__ void zero_cnt_kernel() {
    if (threadIdx.x < NE) g_cnt[threadIdx.x] = 0;
}

// one block per token; 8 warps, warp w does expert w's dot product
__global__ void routing_kernel(const float* __restrict__ x,
                               const float* __restrict__ cw,
                               const float* __restrict__ cb,
                               const float* __restrict__ wealth) {
    int t = blockIdx.x;
    int w = threadIdx.x >> 5, lane = threadIdx.x & 31;
    const float* xr = x + (size_t)t * HD;
    const float* cr = cw + (size_t)w * HD;
    float s = 0.f;
    for (int j = lane; j < HD; j += 32) s += xr[j] * cr[j];
    #pragma unroll
    for (int o = 16; o; o >>= 1) s += __shfl_down_sync(0xffffffffu, s, o);
    __shared__ float bids[NE];
    if (lane == 0) {
        float conf = 1.f / (1.f + expf(-(s + cb[w])));
        bids[w] = conf * wealth[w];
    }
    __syncthreads();
    if (threadIdx.x == 0) {
        int e0 = 0; float b0 = bids[0];
        for (int e = 1; e < NE; e++) if (bids[e] > b0) { b0 = bids[e]; e0 = e; }
        int e1 = -1; float b1 = -1e30f;
        for (int e = 0; e < NE; e++) if (e != e0 && bids[e] > b1) { b1 = bids[e]; e1 = e; }
        float ed = expf(b1 - b0);
        float inv = 1.f / (1.f + ed);
        float w0 = inv, w1 = ed * inv;
        g_eids[2*t] = e0; g_eids[2*t+1] = e1;
        g_wts [2*t] = w0; g_wts [2*t+1] = w1;
        int p0 = atomicAdd(&g_cnt[e0], 1); g_list[e0 * 2 * NTOK + p0] = 2*t;
        int p1 = atomicAdd(&g_cnt[e1], 1); g_list[e1 * 2 * NTOK + p1] = 2*t + 1;
    }
}

// ---------------- generic SGEMM: C[M,N] (+)= A[M,K] * B[N,K]^T ----------------
// BM=BN=128, BK=8, 256 threads, 8x8 per-thread tile.
// Requires M%128==0, K%8==0, 16B-aligned rows (true for all our shapes). N guarded.
template <bool ACCUM>
__global__ void sgemm_nt(const float* __restrict__ A, const float* __restrict__ B,
                         float* __restrict__ C, int M, int N, int K,
                         long long sB, long long sC) {
    const float* Bp = B + (long long)blockIdx.z * sB;
    float* Cp = C + (long long)blockIdx.z * sC;
    int m0 = blockIdx.y * 128, n0 = blockIdx.x * 128;
    __shared__ float As[8][128];
    __shared__ float Bs[8][128];
    int tid = threadIdx.x;
    int tx = tid & 15, ty = tid >> 4;
    float c[8][8] = {};
    int row = tid >> 1, c4 = (tid & 1) * 4;
    const float* Aptr = A + (size_t)(m0 + row) * K + c4;
    const float* Bptr = Bp + (size_t)(n0 + row) * K + c4;
    bool bok = (n0 + row) < N;
    for (int k0 = 0; k0 < K; k0 += 8) {
        float4 av = *(const float4*)(Aptr + k0);
        float4 bv = make_float4(0.f, 0.f, 0.f, 0.f);
        if (bok) bv = *(const float4*)(Bptr + k0);
        As[c4+0][row] = av.x; As[c4+1][row] = av.y; As[c4+2][row] = av.z; As[c4+3][row] = av.w;
        Bs[c4+0][row] = bv.x; Bs[c4+1][row] = bv.y; Bs[c4+2][row] = bv.z; Bs[c4+3][row] = bv.w;
        __syncthreads();
        #pragma unroll
        for (int kk = 0; kk < 8; kk++) {
            float a[8], b[8];
            *(float4*)(a)     = *(const float4*)&As[kk][ty * 8];
            *(float4*)(a + 4) = *(const float4*)&As[kk][ty * 8 + 4];
            *(float4*)(b)     = *(const float4*)&Bs[kk][tx * 8];
            *(float4*)(b + 4) = *(const float4*)&Bs[kk][tx * 8 + 4];
            #pragma unroll
            for (int i = 0; i < 8; i++)
                #pragma unroll
                for (int j = 0; j < 8; j++)
                    c[i][j] += a[i] * b[j];
        }
        __syncthreads();
    }
    #pragma unroll
    for (int i = 0; i < 8; i++) {
        int m = m0 + ty * 8 + i;
        float* crow = Cp + (size_t)m * N;
        #pragma unroll
        for (int j = 0; j < 8; j++) {
            int n = n0 + tx * 8 + j;
            if (n < N) {
                float v = c[i][j];
                if (ACCUM) v += crow[n];
                crow[n] = v;
            }
        }
    }
}

// ---------------- hid kernel: grouped by expert ----------------
// block: 64 token-slot entries x 128 i-columns; computes
// gate = base_gate + s * tg.gB, up = base_up + s * tu.uB, hid = silu(gate)*up
__global__ void hid_kernel(const float* __restrict__ gB, const float* __restrict__ uB) {
    int e = blockIdx.z;
    int n = g_cnt[e];
    int tb = blockIdx.x * 64;
    if (tb >= n) return;
    int i0 = blockIdx.y * 128;
    int tx = threadIdx.x, ty = threadIdx.y;
    int tid = ty * 16 + tx;
    __shared__ int   s_ent[64];
    __shared__ float s_tg[16][64];
    __shared__ float s_tu[16][64];
    __shared__ float s_gB[16][128];
    __shared__ float s_uB[16][128];
    if (tid < 64) {
        int j = tb + tid;
        s_ent[tid] = (j < n) ? g_list[e * 2 * NTOK + j] : -1;
    }
    __syncthreads();
    float accg[4][8] = {}, accu[4][8] = {};
    const float* gBe = gB + (size_t)e * ID * NR;
    const float* uBe = uB + (size_t)e * ID * NR;
    for (int rc = 0; rc < 4; rc++) {
        __syncthreads();
        {   // tg/tu tile: 64 tokens x 16 r
            int tok = tid >> 2, rq = (tid & 3) * 4;
            int ent = s_ent[tok];
            float4 vg = make_float4(0,0,0,0), vu = vg;
            if (ent >= 0) {
                int t = ent >> 1;
                size_t off = ((size_t)e * NTOK + t) * NR + rc * 16 + rq;
                vg = *(const float4*)&g_tg[off];
                vu = *(const float4*)&g_tu[off];
            }
            s_tg[rq+0][tok]=vg.x; s_tg[rq+1][tok]=vg.y; s_tg[rq+2][tok]=vg.z; s_tg[rq+3][tok]=vg.w;
            s_tu[rq+0][tok]=vu.x; s_tu[rq+1][tok]=vu.y; s_tu[rq+2][tok]=vu.z; s_tu[rq+3][tok]=vu.w;
        }
        #pragma unroll
        for (int q = 0; q < 2; q++) {   // gB/uB tile: 128 i x 16 r
            int f = tid * 2 + q;
            int rrow = f >> 2, rq = (f & 3) * 4;
            size_t off = (size_t)(i0 + rrow) * NR + rc * 16 + rq;
            float4 vg = *(const float4*)&gBe[off];
            float4 vu = *(const float4*)&uBe[off];
            s_gB[rq+0][rrow]=vg.x; s_gB[rq+1][rrow]=vg.y; s_gB[rq+2][rrow]=vg.z; s_gB[rq+3][rrow]=vg.w;
            s_uB[rq+0][rrow]=vu.x; s_uB[rq+1][rrow]=vu.y; s_uB[rq+2][rrow]=vu.z; s_uB[rq+3][rrow]=vu.w;
        }
        __syncthreads();
        #pragma unroll
        for (int r = 0; r < 16; r++) {
            float ag[4], au[4], bg[8], bu[8];
            #pragma unroll
            for (int q = 0; q < 4; q++) { ag[q] = s_tg[r][ty*4+q]; au[q] = s_tu[r][ty*4+q]; }
            #pragma unroll
            for (int j = 0; j < 8; j++) { bg[j] = s_gB[r][tx*8+j]; bu[j] = s_uB[r][tx*8+j]; }
            #pragma unroll
            for (int q = 0; q < 4; q++)
                #pragma unroll
                for (int j = 0; j < 8; j++) {
                    accg[q][j] += ag[q] * bg[j];
                    accu[q][j] += au[q] * bu[j];
                }
        }
    }
    #pragma unroll
    for (int q = 0; q < 4; q++) {
        int ent = s_ent[ty * 4 + q];
        if (ent < 0) continue;
        int t = ent >> 1, slot = ent & 1;
        const float* bg = g_basegate + (size_t)t * ID + i0 + tx * 8;
        const float* bu = g_baseup   + (size_t)t * ID + i0 + tx * 8;
        float* ho = g_hid + (size_t)slot * NTOK * ID + (size_t)t * ID + i0 + tx * 8;
        #pragma unroll
        for (int j = 0; j < 8; j++) {
            float gate = bg[j] + SCALE * accg[q][j];
            float up   = bu[j] + SCALE * accu[q][j];
            float sg   = 1.f / (1.f + __expf(-gate));
            ho[j] = gate * sg * up;
        }
    }
}

// ---------------- corr kernel: corr[ent][r] = hid[ent] . dA[e][r] ----------------
__global__ void corr_kernel(const float* __restrict__ dA) {
    int e = blockIdx.y;
    int n = g_cnt[e];
    int tb = blockIdx.x * 64;
    if (tb >= n) return;
    int tid = threadIdx.x;
    int tg4 = tid >> 4;   // token quad
    int rg4 = tid & 15;   // r quad
    __shared__ int   s_ent[64];
    __shared__ float s_h[32][64];
    __shared__ float s_d[32][64];
    if (tid < 64) { int j = tb + tid; s_ent[tid] = (j < n) ? g_list[e*2*NTOK + j] : -1; }
    __syncthreads();
    float acc[4][4] = {};
    const float* dAe = dA + (size_t)e * NR * ID;
    for (int kc = 0; kc < ID; kc += 32) {
        __syncthreads();
        #pragma unroll
        for (int q = 0; q < 2; q++) {
            int f = tid * 2 + q;
            int rrow = f >> 3, kq = (f & 7) * 4;
            int ent = s_ent[rrow];
            float4 v = make_float4(0,0,0,0);
            if (ent >= 0) {
                int t = ent >> 1, slot = ent & 1;
                v = *(const float4*)&g_hid[(size_t)slot*NTOK*ID + (size_t)t*ID + kc + kq];
            }
            s_h[kq+0][rrow]=v.x; s_h[kq+1][rrow]=v.y; s_h[kq+2][rrow]=v.z; s_h[kq+3][rrow]=v.w;
            float4 d = *(const float4*)&dAe[(size_t)rrow * ID + kc + kq];
            s_d[kq+0][rrow]=d.x; s_d[kq+1][rrow]=d.y; s_d[kq+2][rrow]=d.z; s_d[kq+3][rrow]=d.w;
        }
        __syncthreads();
        #pragma unroll
        for (int k = 0; k < 32; k++) {
            float a[4], b[4];
            #pragma unroll
            for (int q = 0; q < 4; q++) { a[q] = s_h[k][tg4*4+q]; b[q] = s_d[k][rg4*4+q]; }
            #pragma unroll
            for (int q = 0; q < 4; q++)
                #pragma unroll
                for (int j = 0; j < 4; j++)
                    acc[q][j] += a[q] * b[j];
        }
    }
    #pragma unroll
    for (int q = 0; q < 4; q++) {
        int ent = s_ent[tg4 * 4 + q];
        if (ent < 0) continue;
        #pragma unroll
        for (int j = 0; j < 4; j++)
            g_corr[ent * NR + rg4 * 4 + j] = acc[q][j];
    }
}

// hmix = w0*hid0 + w1*hid1 (elementwise over T x I, float4)
__global__ void hmix_kernel() {
    size_t gid = (size_t)blockIdx.x * blockDim.x + threadIdx.x;
    size_t idx = gid * 4;
    int t = (int)(idx / ID);
    float w0 = g_wts[2*t], w1 = g_wts[2*t+1];
    float4 h0 = *(const float4*)&g_hid[idx];
    float4 h1 = *(const float4*)&g_hid[(size_t)NTOK * ID + idx];
    float4 o;
    o.x = w0*h0.x + w1*h1.x; o.y = w0*h0.y + w1*h1.y;
    o.z = w0*h0.z + w1*h1.z; o.w = w0*h0.w + w1*h1.w;
    *(float4*)&g_hmix[idx] = o;
}

// cvec[t][e*64+r] = s * sum_k w_k * corr_k[t][r] * (e_k == e)
__global__ void cvec_kernel() {
    int idx = blockIdx.x * 256 + threadIdx.x;
    int t = idx >> 9, j = idx & 511;
    int e = j >> 6, r = j & 63;
    float v = 0.f;
    if (e == g_eids[2*t])   v += SCALE * g_wts[2*t]   * g_corr[(2*t)   * NR + r];
    if (e == g_eids[2*t+1]) v += SCALE * g_wts[2*t+1] * g_corr[(2*t+1) * NR + r];
    g_cvec[idx] = v;
}

// dball[h][e*64+r] = dB[e][h][r]
__global__ void dball_kernel(const float* __restrict__ dB) {
    int idx = blockIdx.x * 256 + threadIdx.x;
    int h = idx >> 9, j = idx & 511;
    int e = j >> 6, r = j & 63;
    g_dball[idx] = dB[((size_t)e * HD + h) * NR + r];
}

// ---------------- launch ----------------
extern "C" void kernel_launch(void* const* d_in, const int* in_sizes, int n_in,
                              void* d_out, int out_size) {
    const float* x      = (const float*)d_in[0];
    const float* conf_w = (const float*)d_in[1];
    const float* conf_b = (const float*)d_in[2];
    const float* wealth = (const float*)d_in[3];
    const float* bgw    = (const float*)d_in[4];
    const float* buw    = (const float*)d_in[5];
    const float* bdw    = (const float*)d_in[6];
    const float* gA     = (const float*)d_in[7];
    const float* gB     = (const float*)d_in[8];
    const float* uA     = (const float*)d_in[9];
    const float* uB     = (const float*)d_in[10];
    const float* dA     = (const float*)d_in[11];
    const float* dB     = (const float*)d_in[12];
    float* out = (float*)d_out;

    float *p_basegate, *p_baseup, *p_hmix, *p_tg, *p_tu, *p_cvec, *p_dball;
    cudaGetSymbolAddress((void**)&p_basegate, g_basegate);
    cudaGetSymbolAddress((void**)&p_baseup,   g_baseup);
    cudaGetSymbolAddress((void**)&p_hmix,     g_hmix);
    cudaGetSymbolAddress((void**)&p_tg,       g_tg);
    cudaGetSymbolAddress((void**)&p_tu,       g_tu);
    cudaGetSymbolAddress((void**)&p_cvec,     g_cvec);
    cudaGetSymbolAddress((void**)&p_dball,    g_dball);

    zero_cnt_kernel<<<1, 32>>>();
    routing_kernel<<<NTOK, 256>>>(x, conf_w, conf_b, wealth);

    // base_gate = X @ bgw^T, base_up = X @ buw^T
    {
        dim3 grid(ID / 128, NTOK / 128, 1);
        sgemm_nt<false><<<grid, 256>>>(x, bgw, p_basegate, NTOK, ID, HD, 0, 0);
        sgemm_nt<false><<<grid, 256>>>(x, buw, p_baseup,   NTOK, ID, HD, 0, 0);
    }
    // LoRA A: tg[e] = X @ gA[e]^T, tu[e] = X @ uA[e]^T (batched over experts)
    {
        dim3 grid(1, NTOK / 128, NE);
        sgemm_nt<false><<<grid, 256>>>(x, gA, p_tg, NTOK, NR, HD,
                                       (long long)NR * HD, (long long)NTOK * NR);
        sgemm_nt<false><<<grid, 256>>>(x, uA, p_tu, NTOK, NR, HD,
                                       (long long)NR * HD, (long long)NTOK * NR);
    }
    // hid (grouped by expert)
    {
        dim3 grid(2 * NTOK / 64, ID / 128, NE);
        hid_kernel<<<grid, dim3(16, 16)>>>(gB, uB);
    }
    hmix_kernel<<<(int)(((size_t)NTOK * ID / 4) / 256), 256>>>();
    {
        dim3 grid(2 * NTOK / 64, NE);
        corr_kernel<<<grid, 256>>>(dA);
    }
    cvec_kernel<<<NTOK * (NE * NR) / 256, 256>>>();
    dball_kernel<<<HD * (NE * NR) / 256, 256>>>(dB);

    // out = hmix @ bdw^T ; out += cvec @ dball^T
    {
        dim3 grid(HD / 128, NTOK / 128, 1);
        sgemm_nt<false><<<grid, 256>>>(p_hmix, bdw, out, NTOK, HD, ID, 0, 0);
        sgemm_nt<true><<<grid, 256>>>(p_cvec, p_dball, out, NTOK, HD, NE * NR, 0, 0);
    }
}

// round 3
// speedup vs baseline: 1.8017x; 1.8017x over previous
#include <cuda_runtime.h>
#include <cstdint>
#include <math.h>

#define NTOK 2048
#define HD   2048
#define ID   7168
#define NE   8
#define NR   64
#define EC   (NE*NR)       // 512
#define KDOWN (ID+EC)      // 7680
#define SCALE 0.25f

#define PAD 132            // floats per k-row in SMEM tile
#define KT  (32*PAD)       // uints per tile
#define SMEM_BYTES (2*2*KT*4)   // 2 stages x (A,B) = 67584 B

// ---------------- scratch (__device__ globals) ----------------
__device__ float g_basegate[(size_t)NTOK*ID];
__device__ float g_baseup [(size_t)NTOK*ID];
__device__ float g_tg     [NTOK*EC];
__device__ float g_tu     [NTOK*EC];
__device__ float g_amg    [2*NTOK*EC];
__device__ float g_amu    [2*NTOK*EC];
__device__ float g_gBall  [(size_t)ID*EC];
__device__ float g_uBall  [(size_t)ID*EC];
__device__ float g_gc     [(size_t)2*NTOK*ID];
__device__ float g_uc     [(size_t)2*NTOK*ID];
__device__ float g_hid01  [(size_t)2*NTOK*ID];
__device__ float g_hmixext[(size_t)NTOK*KDOWN];
__device__ float g_corrall[2*NTOK*EC];
__device__ float g_bcomb  [(size_t)HD*KDOWN];
__device__ int   g_eids   [2*NTOK];
__device__ float g_wts    [2*NTOK];

// ---------------- helpers ----------------
__device__ __forceinline__ uint32_t f2tf32(float x){
    uint32_t r;
    asm("cvt.rna.tf32.f32 %0, %1;" : "=r"(r) : "f"(x));
    return r;
}

__device__ __forceinline__ void mma_tf32(float* c, const uint32_t* a, const uint32_t* b){
    asm volatile(
        "mma.sync.aligned.m16n8k8.row.col.f32.tf32.tf32.f32 "
        "{%0,%1,%2,%3}, {%4,%5,%6,%7}, {%8,%9}, {%0,%1,%2,%3};"
        : "+f"(c[0]), "+f"(c[1]), "+f"(c[2]), "+f"(c[3])
        : "r"(a[0]), "r"(a[1]), "r"(a[2]), "r"(a[3]), "r"(b[0]), "r"(b[1]));
}

// ---------------- tf32 mma.sync GEMM: C[M,N] = A[M,K] * B[N,K]^T ----------------
// 128x128x32 CTA tile, 256 threads (8 warps, 2x4 of 64x32), double-buffered SMEM.
// Requires M%128==0, N%128==0, K%32==0, rows 16B-aligned.
__global__ __launch_bounds__(256, 1) void gemm_tf32(
        const float* __restrict__ A, const float* __restrict__ B,
        float* __restrict__ C, int M, int N, int K){
    extern __shared__ uint32_t sm[];
    const int tid = threadIdx.x;
    const int wid = tid >> 5, lane = tid & 31;
    const int wm = wid >> 2, wn = wid & 3;      // warp 2x4
    const int grp = lane >> 2, tig = lane & 3;
    const int m0 = blockIdx.y << 7, n0 = blockIdx.x << 7;

    // LDG mapping: l7 = k-float4 (0..7), rb = base row (0..31); q adds 32 rows
    const int l7 = tid & 7, rb = tid >> 3;
    const float* Ag = A + (size_t)(m0 + rb) * K + (l7 << 2);
    const float* Bg = B + (size_t)(n0 + rb) * K + (l7 << 2);
    const size_t qs = (size_t)32 * K;

    const int nch = K >> 5;
    float4 pa[4], pb[4];

    // preamble: load + store chunk 0
    #pragma unroll
    for (int q = 0; q < 4; q++){
        pa[q] = *(const float4*)(Ag + qs * q);
        pb[q] = *(const float4*)(Bg + qs * q);
    }
    {
        uint32_t* as = sm; uint32_t* bs = sm + KT;
        const int kb = l7 << 2;
        #pragma unroll
        for (int q = 0; q < 4; q++){
            int row = rb + (q << 5);
            as[(kb+0)*PAD + row] = f2tf32(pa[q].x);
            as[(kb+1)*PAD + row] = f2tf32(pa[q].y);
            as[(kb+2)*PAD + row] = f2tf32(pa[q].z);
            as[(kb+3)*PAD + row] = f2tf32(pa[q].w);
            bs[(kb+0)*PAD + row] = f2tf32(pb[q].x);
            bs[(kb+1)*PAD + row] = f2tf32(pb[q].y);
            bs[(kb+2)*PAD + row] = f2tf32(pb[q].z);
            bs[(kb+3)*PAD + row] = f2tf32(pb[q].w);
        }
    }
    __syncthreads();

    float acc[4][4][4] = {};

    for (int c = 0; c < nch; c++){
        // prefetch next chunk
        if (c + 1 < nch){
            const int k0 = (c + 1) << 5;
            #pragma unroll
            for (int q = 0; q < 4; q++){
                pa[q] = *(const float4*)(Ag + qs * q + k0);
                pb[q] = *(const float4*)(Bg + qs * q + k0);
            }
        }
        // compute current buffer
        {
            const uint32_t* as = sm + (c & 1) * 2 * KT;
            const uint32_t* bs = as + KT;
            #pragma unroll
            for (int kk = 0; kk < 4; kk++){
                const int k = (kk << 3) + tig;
                uint32_t af[4][4], bf[4][2];
                #pragma unroll
                for (int i = 0; i < 4; i++){
                    int mb = (wm << 6) + (i << 4) + grp;
                    af[i][0] = as[k*PAD + mb];
                    af[i][1] = as[k*PAD + mb + 8];
                    af[i][2] = as[(k+4)*PAD + mb];
                    af[i][3] = as[(k+4)*PAD + mb + 8];
                }
                #pragma unroll
                for (int j = 0; j < 4; j++){
                    int nb = (wn << 5) + (j << 3) + grp;
                    bf[j][0] = bs[k*PAD + nb];
                    bf[j][1] = bs[(k+4)*PAD + nb];
                }
                #pragma unroll
                for (int i = 0; i < 4; i++)
                    #pragma unroll
                    for (int j = 0; j < 4; j++)
                        mma_tf32(acc[i][j], af[i], bf[j]);
            }
        }
        // store next chunk into other buffer
        if (c + 1 < nch){
            uint32_t* as = sm + ((c + 1) & 1) * 2 * KT;
            uint32_t* bs = as + KT;
            const int kb = l7 << 2;
            #pragma unroll
            for (int q = 0; q < 4; q++){
                int row = rb + (q << 5);
                as[(kb+0)*PAD + row] = f2tf32(pa[q].x);
                as[(kb+1)*PAD + row] = f2tf32(pa[q].y);
                as[(kb+2)*PAD + row] = f2tf32(pa[q].z);
                as[(kb+3)*PAD + row] = f2tf32(pa[q].w);
                bs[(kb+0)*PAD + row] = f2tf32(pb[q].x);
                bs[(kb+1)*PAD + row] = f2tf32(pb[q].y);
                bs[(kb+2)*PAD + row] = f2tf32(pb[q].z);
                bs[(kb+3)*PAD + row] = f2tf32(pb[q].w);
            }
            __syncthreads();
        }
    }

    // epilogue
    #pragma unroll
    for (int i = 0; i < 4; i++){
        int r0 = m0 + (wm << 6) + (i << 4) + grp;
        #pragma unroll
        for (int j = 0; j < 4; j++){
            int col = n0 + (wn << 5) + (j << 3) + (tig << 1);
            float2 v0 = make_float2(acc[i][j][0], acc[i][j][1]);
            float2 v1 = make_float2(acc[i][j][2], acc[i][j][3]);
            *(float2*)(C + (size_t)r0 * N + col) = v0;
            *(float2*)(C + (size_t)(r0 + 8) * N + col) = v1;
        }
    }
}

// ---------------- routing: one block per token, 8 warps ----------------
__global__ void routing_kernel(const float* __restrict__ x,
                               const float* __restrict__ cw,
                               const float* __restrict__ cb,
                               const float* __restrict__ wealth){
    int t = blockIdx.x;
    int w = threadIdx.x >> 5, lane = threadIdx.x & 31;
    const float* xr = x + (size_t)t * HD;
    const float* cr = cw + (size_t)w * HD;
    float s = 0.f;
    for (int j = lane; j < HD; j += 32) s += xr[j] * cr[j];
    #pragma unroll
    for (int o = 16; o; o >>= 1) s += __shfl_down_sync(0xffffffffu, s, o);
    __shared__ float bids[NE];
    if (lane == 0){
        float conf = 1.f / (1.f + expf(-(s + cb[w])));
        bids[w] = conf * wealth[w];
    }
    __syncthreads();
    if (threadIdx.x == 0){
        int e0 = 0; float b0 = bids[0];
        for (int e = 1; e < NE; e++) if (bids[e] > b0){ b0 = bids[e]; e0 = e; }
        int e1 = -1; float b1 = -1e30f;
        for (int e = 0; e < NE; e++) if (e != e0 && bids[e] > b1){ b1 = bids[e]; e1 = e; }
        float ed = expf(b1 - b0);
        float inv = 1.f / (1.f + ed);
        g_eids[2*t] = e0; g_eids[2*t+1] = e1;
        g_wts [2*t] = inv; g_wts [2*t+1] = ed * inv;
    }
}

// ---------------- masked LoRA-A scatter: amg/amu [2T,512] ----------------
__global__ void amask_kernel(){
    int idx = blockIdx.x * 256 + threadIdx.x;       // 2*NTOK*EC
    int row = idx >> 9, j = idx & 511;
    int k = row >> 11, t = row & 2047;
    int e = j >> 6;
    bool sel = (e == g_eids[2*t + k]);
    g_amg[idx] = sel ? g_tg[t*EC + j] : 0.f;
    g_amu[idx] = sel ? g_tu[t*EC + j] : 0.f;
}

// gBall[i][e*64+r] = gB[e][i][r]; same for uBall
__global__ void packB_kernel(const float* __restrict__ gB, const float* __restrict__ uB){
    size_t idx = (size_t)blockIdx.x * 256 + threadIdx.x;  // ID*EC
    int i = (int)(idx >> 9); int j = (int)(idx & 511);
    int e = j >> 6, r = j & 63;
    size_t src = ((size_t)e * ID + i) * NR + r;
    g_gBall[idx] = gB[src];
    g_uBall[idx] = uB[src];
}

// bcomb[h][k] = bdw[h][k] (k<ID) else dB[e][h][r]
__global__ void bcomb_kernel(const float* __restrict__ bdw, const float* __restrict__ dB){
    size_t idx = (size_t)blockIdx.x * 256 + threadIdx.x;  // HD*KDOWN
    int h = (int)(idx / KDOWN); int k = (int)(idx % KDOWN);
    float v;
    if (k < ID) v = bdw[(size_t)h * ID + k];
    else { int j = k - ID; int e = j >> 6; int r = j & 63;
           v = dB[((size_t)e * HD + h) * NR + r]; }
    g_bcomb[idx] = v;
}

// hid elementwise: h_k = silu(bg + s*gc_k)*(bu + s*uc_k); hmix = w0 h0 + w1 h1
__global__ void hid_kernel(){
    size_t i4 = (size_t)blockIdx.x * 256 + threadIdx.x;   // NTOK*ID/4
    size_t idx = i4 << 2;
    int t = (int)(idx / ID); int col = (int)(idx % ID);
    float w0 = g_wts[2*t], w1 = g_wts[2*t+1];
    float4 bg = *(const float4*)&g_basegate[idx];
    float4 bu = *(const float4*)&g_baseup[idx];
    size_t o1 = (size_t)(NTOK + t) * ID + col;
    float4 gc0 = *(const float4*)&g_gc[idx], gc1 = *(const float4*)&g_gc[o1];
    float4 uc0 = *(const float4*)&g_uc[idx], uc1 = *(const float4*)&g_uc[o1];
    float4 h0, h1, hm;
    {
        float g, u, sg;
        g = bg.x + SCALE*gc0.x; u = bu.x + SCALE*uc0.x; sg = 1.f/(1.f+__expf(-g)); h0.x = g*sg*u;
        g = bg.y + SCALE*gc0.y; u = bu.y + SCALE*uc0.y; sg = 1.f/(1.f+__expf(-g)); h0.y = g*sg*u;
        g = bg.z + SCALE*gc0.z; u = bu.z + SCALE*uc0.z; sg = 1.f/(1.f+__expf(-g)); h0.z = g*sg*u;
        g = bg.w + SCALE*gc0.w; u = bu.w + SCALE*uc0.w; sg = 1.f/(1.f+__expf(-g)); h0.w = g*sg*u;
        g = bg.x + SCALE*gc1.x; u = bu.x + SCALE*uc1.x; sg = 1.f/(1.f+__expf(-g)); h1.x = g*sg*u;
        g = bg.y + SCALE*gc1.y; u = bu.y + SCALE*uc1.y; sg = 1.f/(1.f+__expf(-g)); h1.y = g*sg*u;
        g = bg.z + SCALE*gc1.z; u = bu.z + SCALE*uc1.z; sg = 1.f/(1.f+__expf(-g)); h1.z = g*sg*u;
        g = bg.w + SCALE*gc1.w; u = bu.w + SCALE*uc1.w; sg = 1.f/(1.f+__expf(-g)); h1.w = g*sg*u;
    }
    hm.x = w0*h0.x + w1*h1.x; hm.y = w0*h0.y + w1*h1.y;
    hm.z = w0*h0.z + w1*h1.z; hm.w = w0*h0.w + w1*h1.w;
    *(float4*)&g_hid01[idx] = h0;
    *(float4*)&g_hid01[o1]  = h1;
    *(float4*)&g_hmixext[(size_t)t * KDOWN + col] = hm;
}

// cvec tail columns of hmixext
__global__ void cvec_kernel(){
    int idx = blockIdx.x * 256 + threadIdx.x;   // NTOK*EC
    int t = idx >> 9, j = idx & 511;
    int e = j >> 6;
    float v = 0.f;
    if (e == g_eids[2*t])   v += g_wts[2*t]   * g_corrall[(size_t)t * EC + j];
    if (e == g_eids[2*t+1]) v += g_wts[2*t+1] * g_corrall[(size_t)(NTOK + t) * EC + j];
    g_hmixext[(size_t)t * KDOWN + ID + j] = SCALE * v;
}

// ---------------- launch ----------------
static void launch_gemm(const float* A, const float* B, float* C, int M, int N, int K){
    static bool attr_set = false;
    if (!attr_set){
        cudaFuncSetAttribute(gemm_tf32, cudaFuncAttributeMaxDynamicSharedMemorySize, SMEM_BYTES);
        attr_set = true;
    }
    dim3 grid(N / 128, M / 128);
    gemm_tf32<<<grid, 256, SMEM_BYTES>>>(A, B, C, M, N, K);
}

extern "C" void kernel_launch(void* const* d_in, const int* in_sizes, int n_in,
                              void* d_out, int out_size){
    const float* x      = (const float*)d_in[0];
    const float* conf_w = (const float*)d_in[1];
    const float* conf_b = (const float*)d_in[2];
    const float* wealth = (const float*)d_in[3];
    const float* bgw    = (const float*)d_in[4];
    const float* buw    = (const float*)d_in[5];
    const float* bdw    = (const float*)d_in[6];
    const float* gA     = (const float*)d_in[7];   // [E,R,H] == [512,2048]
    const float* gB     = (const float*)d_in[8];
    const float* uA     = (const float*)d_in[9];   // [512,2048]
    const float* uB     = (const float*)d_in[10];
    const float* dA     = (const float*)d_in[11];  // [E,R,I] == [512,7168]
    const float* dB     = (const float*)d_in[12];
    float* out = (float*)d_out;

    float *p_basegate, *p_baseup, *p_tg, *p_tu, *p_amg, *p_amu,
          *p_gBall, *p_uBall, *p_gc, *p_uc, *p_hid01, *p_hmixext,
          *p_corrall, *p_bcomb;
    cudaGetSymbolAddress((void**)&p_basegate, g_basegate);
    cudaGetSymbolAddress((void**)&p_baseup,   g_baseup);
    cudaGetSymbolAddress((void**)&p_tg,       g_tg);
    cudaGetSymbolAddress((void**)&p_tu,       g_tu);
    cudaGetSymbolAddress((void**)&p_amg,      g_amg);
    cudaGetSymbolAddress((void**)&p_amu,      g_amu);
    cudaGetSymbolAddress((void**)&p_gBall,    g_gBall);
    cudaGetSymbolAddress((void**)&p_uBall,    g_uBall);
    cudaGetSymbolAddress((void**)&p_gc,       g_gc);
    cudaGetSymbolAddress((void**)&p_uc,       g_uc);
    cudaGetSymbolAddress((void**)&p_hid01,    g_hid01);
    cudaGetSymbolAddress((void**)&p_hmixext,  g_hmixext);
    cudaGetSymbolAddress((void**)&p_corrall,  g_corrall);
    cudaGetSymbolAddress((void**)&p_bcomb,    g_bcomb);

    routing_kernel<<<NTOK, 256>>>(x, conf_w, conf_b, wealth);

    // packing (independent of routing)
    packB_kernel<<<(ID*EC)/256, 256>>>(gB, uB);
    bcomb_kernel<<<(HD*KDOWN)/256, 256>>>(bdw, dB);

    // base projections + LoRA-A (all experts stacked)
    launch_gemm(x, bgw, p_basegate, NTOK, ID, HD);
    launch_gemm(x, buw, p_baseup,   NTOK, ID, HD);
    launch_gemm(x, gA,  p_tg, NTOK, EC, HD);
    launch_gemm(x, uA,  p_tu, NTOK, EC, HD);

    // masked-dense LoRA-B expansion (slot-major M=4096)
    amask_kernel<<<(2*NTOK*EC)/256, 256>>>();
    launch_gemm(p_amg, p_gBall, p_gc, 2*NTOK, ID, EC);
    launch_gemm(p_amu, p_uBall, p_uc, 2*NTOK, ID, EC);

    // elementwise silu/mul + weighted mix
    hid_kernel<<<(NTOK*ID/4)/256, 256>>>();

    // down-LoRA correction via dense dA projection
    launch_gemm(p_hid01, dA, p_corrall, 2*NTOK, EC, ID);
    cvec_kernel<<<(NTOK*EC)/256, 256>>>();

    // fused down projection: out = [hmix | cvec] @ [bdw | dBall]^T
    launch_gemm(p_hmixext, p_bcomb, out, NTOK, HD, KDOWN);
}

// round 4
// speedup vs baseline: 3.1438x; 1.7449x over previous
#include <cuda_runtime.h>
#include <cstdint>
#include <math.h>

#define NTOK 2048
#define HD   2048
#define ID   7168
#define NE   8
#define NR   64
#define EC   (NE*NR)       // 512
#define KDOWN (ID+EC)      // 7680
#define SCALE 0.25f

// GEMM tiling
#define BM 256
#define BN 128
#define BK 32
#define STAGES 4
#define STAGE_FLOATS 12288          // A 8192 + B 4096
#define STAGE_BYTES  49152
#define SMEM_BYTES   (STAGES*STAGE_BYTES)   // 196608

// ---------------- scratch (__device__ globals) ----------------
__device__ float g_basegate[(size_t)NTOK*ID];
__device__ float g_baseup [(size_t)NTOK*ID];
__device__ float g_tg     [NTOK*EC];
__device__ float g_tu     [NTOK*EC];
__device__ float g_amg    [2*NTOK*EC];
__device__ float g_amu    [2*NTOK*EC];
__device__ float g_gBall  [(size_t)ID*EC];
__device__ float g_uBall  [(size_t)ID*EC];
__device__ float g_gc     [(size_t)2*NTOK*ID];
__device__ float g_uc     [(size_t)2*NTOK*ID];
__device__ float g_hid01  [(size_t)2*NTOK*ID];
__device__ float g_hmixext[(size_t)NTOK*KDOWN];
__device__ float g_corrall[2*NTOK*EC];
__device__ float g_bcomb  [(size_t)HD*KDOWN];
__device__ int   g_eids   [2*NTOK];
__device__ float g_wts    [2*NTOK];
// tf32-preconverted operands
__device__ float g_xc     [(size_t)NTOK*HD];
__device__ float g_bgwc   [(size_t)ID*HD];
__device__ float g_buwc   [(size_t)ID*HD];
__device__ float g_gac    [EC*HD];
__device__ float g_uac    [EC*HD];
__device__ float g_dac    [(size_t)EC*ID];

// ---------------- helpers ----------------
__device__ __forceinline__ float f2tf32f(float x){
    uint32_t r;
    asm("cvt.rna.tf32.f32 %0, %1;" : "=r"(r) : "f"(x));
    return __uint_as_float(r);
}

__device__ __forceinline__ void mma_tf32(float* c, const uint32_t* a, const uint32_t* b){
    asm volatile(
        "mma.sync.aligned.m16n8k8.row.col.f32.tf32.tf32.f32 "
        "{%0,%1,%2,%3}, {%4,%5,%6,%7}, {%8,%9}, {%0,%1,%2,%3};"
        : "+f"(c[0]), "+f"(c[1]), "+f"(c[2]), "+f"(c[3])
        : "r"(a[0]), "r"(a[1]), "r"(a[2]), "r"(a[3]), "r"(b[0]), "r"(b[1]));
}

__device__ __forceinline__ void cp16(uint32_t smaddr, const void* g){
    asm volatile("cp.async.cg.shared.global [%0], [%1], 16;"
                 :: "r"(smaddr), "l"(g));
}
__device__ __forceinline__ void cp_commit(){
    asm volatile("cp.async.commit_group;" ::: "memory");
}
template<int N> __device__ __forceinline__ void cp_wait(){
    asm volatile("cp.async.wait_group %0;" :: "n"(N) : "memory");
}

// ---------------- tf32 multistage GEMM: C[M,N] = A[M,K]*B[N,K]^T ----------------
// A,B must be tf32-preconverted fp32 bit patterns. M%256==0, N%128==0, K%32==0.
__global__ __launch_bounds__(256, 1) void gemm_tf32(
        const float* __restrict__ A, const float* __restrict__ B,
        float* __restrict__ C, int M, int N, int K){
    extern __shared__ float sm[];
    const int tid = threadIdx.x;
    const int wid = tid >> 5, lane = tid & 31;
    const int wm = wid >> 1, wn = wid & 1;      // 4x2 warps
    const int grp = lane >> 2, tig = lane & 3;
    const int m0 = blockIdx.y * BM, n0 = blockIdx.x * BN;

    uint32_t smem_base;
    {
        uint64_t t = __cvta_generic_to_shared(sm);
        smem_base = (uint32_t)t;
    }

    // --- cp.async source/dst mapping ---
    const int rA = tid >> 3;             // 0..31 base row
    const int cc = (tid & 7) << 2;       // float col of this 16B chunk
    const uint32_t xmask = ((uint32_t)(rA & 7)) << 2;
    const uint32_t ccs = (uint32_t)cc ^ xmask;        // swizzled col (16B aligned)
    const float* Agp = A + (size_t)(m0 + rA) * K + cc;
    const float* Bgp = B + (size_t)(n0 + rA) * K + cc;
    const size_t rstep = (size_t)32 * K;

    uint32_t dstA[8], dstB[4];
    #pragma unroll
    for (int q = 0; q < 8; q++) dstA[q] = ((uint32_t)(rA + 32*q) * 32u + ccs) * 4u;
    #pragma unroll
    for (int q = 0; q < 4; q++) dstB[q] = 32768u + ((uint32_t)(rA + 32*q) * 32u + ccs) * 4u;

    const int nch = K >> 5;

    // prologue: load first STAGES-1 chunks
    #pragma unroll
    for (int s = 0; s < STAGES-1; s++){
        if (s < nch){
            uint32_t base = smem_base + (uint32_t)s * STAGE_BYTES;
            const float* ag = Agp + (s << 5);
            const float* bg = Bgp + (s << 5);
            #pragma unroll
            for (int q = 0; q < 8; q++) cp16(base + dstA[q], ag + rstep * q);
            #pragma unroll
            for (int q = 0; q < 4; q++) cp16(base + dstB[q], bg + rstep * q);
        }
        cp_commit();
    }

    // --- fragment addressing (floats within stage) ---
    const uint32_t gx = (uint32_t)grp << 2;
    uint32_t aRow[4], bRow[8];
    #pragma unroll
    for (int i = 0; i < 4; i++) aRow[i] = (uint32_t)(wm*64 + i*16 + grp) * 32u;
    #pragma unroll
    for (int j = 0; j < 8; j++) bRow[j] = 8192u + (uint32_t)(wn*64 + j*8 + grp) * 32u;

    float acc[4][8][4];
    #pragma unroll
    for (int i = 0; i < 4; i++)
        #pragma unroll
        for (int j = 0; j < 8; j++)
            #pragma unroll
            for (int q = 0; q < 4; q++) acc[i][j][q] = 0.f;

    for (int c = 0; c < nch; c++){
        cp_wait<STAGES-2>();
        __syncthreads();

        // issue loads for chunk c+STAGES-1 into buffer (c-1)&3 (safe after sync)
        if (c + STAGES-1 < nch){
            const int cn = c + STAGES-1;
            uint32_t base = smem_base + (uint32_t)(cn & (STAGES-1)) * STAGE_BYTES;
            const float* ag = Agp + (cn << 5);
            const float* bg = Bgp + (cn << 5);
            #pragma unroll
            for (int q = 0; q < 8; q++) cp16(base + dstA[q], ag + rstep * q);
            #pragma unroll
            for (int q = 0; q < 4; q++) cp16(base + dstB[q], bg + rstep * q);
        }
        cp_commit();

        const uint32_t* st = (const uint32_t*)(sm + (size_t)(c & (STAGES-1)) * STAGE_FLOATS);
        #pragma unroll
        for (int kk = 0; kk < 4; kk++){
            const uint32_t k0 = ((uint32_t)(kk*8) + tig) ^ gx;
            const uint32_t k1 = ((uint32_t)(kk*8) + tig + 4u) ^ gx;
            uint32_t af[4][4], bf[8][2];
            #pragma unroll
            for (int i = 0; i < 4; i++){
                af[i][0] = st[aRow[i] + k0];
                af[i][1] = st[aRow[i] + 256u + k0];
                af[i][2] = st[aRow[i] + k1];
                af[i][3] = st[aRow[i] + 256u + k1];
            }
            #pragma unroll
            for (int j = 0; j < 8; j++){
                bf[j][0] = st[bRow[j] + k0];
                bf[j][1] = st[bRow[j] + k1];
            }
            #pragma unroll
            for (int i = 0; i < 4; i++)
                #pragma unroll
                for (int j = 0; j < 8; j++)
                    mma_tf32(acc[i][j], af[i], bf[j]);
        }
    }

    // epilogue
    #pragma unroll
    for (int i = 0; i < 4; i++){
        int r0 = m0 + wm*64 + i*16 + grp;
        float* cr0 = C + (size_t)r0 * N;
        float* cr1 = C + (size_t)(r0 + 8) * N;
        #pragma unroll
        for (int j = 0; j < 8; j++){
            int col = n0 + wn*64 + j*8 + (tig << 1);
            *(float2*)(cr0 + col) = make_float2(acc[i][j][0], acc[i][j][1]);
            *(float2*)(cr1 + col) = make_float2(acc[i][j][2], acc[i][j][3]);
        }
    }
}

// ---------------- tf32 conversion pass ----------------
__global__ void conv_kernel(const float* __restrict__ in, float* __restrict__ out){
    size_t i4 = ((size_t)blockIdx.x * 256 + threadIdx.x) << 2;
    float4 v = *(const float4*)(in + i4);
    v.x = f2tf32f(v.x); v.y = f2tf32f(v.y); v.z = f2tf32f(v.z); v.w = f2tf32f(v.w);
    *(float4*)(out + i4) = v;
}

// ---------------- routing: one block per token, 8 warps ----------------
__global__ void routing_kernel(const float* __restrict__ x,
                               const float* __restrict__ cw,
                               const float* __restrict__ cb,
                               const float* __restrict__ wealth){
    int t = blockIdx.x;
    int w = threadIdx.x >> 5, lane = threadIdx.x & 31;
    const float* xr = x + (size_t)t * HD;
    const float* cr = cw + (size_t)w * HD;
    float s = 0.f;
    for (int j = lane; j < HD; j += 32) s += xr[j] * cr[j];
    #pragma unroll
    for (int o = 16; o; o >>= 1) s += __shfl_down_sync(0xffffffffu, s, o);
    __shared__ float bids[NE];
    if (lane == 0){
        float conf = 1.f / (1.f + expf(-(s + cb[w])));
        bids[w] = conf * wealth[w];
    }
    __syncthreads();
    if (threadIdx.x == 0){
        int e0 = 0; float b0 = bids[0];
        for (int e = 1; e < NE; e++) if (bids[e] > b0){ b0 = bids[e]; e0 = e; }
        int e1 = -1; float b1 = -1e30f;
        for (int e = 0; e < NE; e++) if (e != e0 && bids[e] > b1){ b1 = bids[e]; e1 = e; }
        float ed = expf(b1 - b0);
        float inv = 1.f / (1.f + ed);
        g_eids[2*t] = e0; g_eids[2*t+1] = e1;
        g_wts [2*t] = inv; g_wts [2*t+1] = ed * inv;
    }
}

// ---------------- masked LoRA-A scatter (tf32 output) ----------------
__global__ void amask_kernel(){
    int idx = blockIdx.x * 256 + threadIdx.x;       // 2*NTOK*EC
    int row = idx >> 9, j = idx & 511;
    int k = row >> 11, t = row & 2047;
    int e = j >> 6;
    bool sel = (e == g_eids[2*t + k]);
    g_amg[idx] = sel ? f2tf32f(g_tg[t*EC + j]) : 0.f;
    g_amu[idx] = sel ? f2tf32f(g_tu[t*EC + j]) : 0.f;
}

// gBall[i][e*64+r] = tf32(gB[e][i][r]); same for uBall
__global__ void packB_kernel(const float* __restrict__ gB, const float* __restrict__ uB){
    size_t idx = (size_t)blockIdx.x * 256 + threadIdx.x;  // ID*EC
    int i = (int)(idx >> 9); int j = (int)(idx & 511);
    int e = j >> 6, r = j & 63;
    size_t src = ((size_t)e * ID + i) * NR + r;
    g_gBall[idx] = f2tf32f(gB[src]);
    g_uBall[idx] = f2tf32f(uB[src]);
}

// bcomb[h][k] = tf32( bdw[h][k] (k<ID) else dB[e][h][r] )
__global__ void bcomb_kernel(const float* __restrict__ bdw, const float* __restrict__ dB){
    size_t idx = (size_t)blockIdx.x * 256 + threadIdx.x;  // HD*KDOWN
    int h = (int)(idx / KDOWN); int k = (int)(idx % KDOWN);
    float v;
    if (k < ID) v = bdw[(size_t)h * ID + k];
    else { int j = k - ID; int e = j >> 6; int r = j & 63;
           v = dB[((size_t)e * HD + h) * NR + r]; }
    g_bcomb[idx] = f2tf32f(v);
}

// hid elementwise: h_k = silu(bg + s*gc_k)*(bu + s*uc_k); hmix = w0 h0 + w1 h1
// outputs tf32-rounded (feed GEMMs)
__global__ void hid_kernel(){
    size_t i4 = (size_t)blockIdx.x * 256 + threadIdx.x;   // NTOK*ID/4
    size_t idx = i4 << 2;
    int t = (int)(idx / ID); int col = (int)(idx % ID);
    float w0 = g_wts[2*t], w1 = g_wts[2*t+1];
    float4 bg = *(const float4*)&g_basegate[idx];
    float4 bu = *(const float4*)&g_baseup[idx];
    size_t o1 = (size_t)(NTOK + t) * ID + col;
    float4 gc0 = *(const float4*)&g_gc[idx], gc1 = *(const float4*)&g_gc[o1];
    float4 uc0 = *(const float4*)&g_uc[idx], uc1 = *(const float4*)&g_uc[o1];
    float4 h0, h1, hm;
    {
        float g, u, sg;
        g = bg.x + SCALE*gc0.x; u = bu.x + SCALE*uc0.x; sg = 1.f/(1.f+__expf(-g)); h0.x = g*sg*u;
        g = bg.y + SCALE*gc0.y; u = bu.y + SCALE*uc0.y; sg = 1.f/(1.f+__expf(-g)); h0.y = g*sg*u;
        g = bg.z + SCALE*gc0.z; u = bu.z + SCALE*uc0.z; sg = 1.f/(1.f+__expf(-g)); h0.z = g*sg*u;
        g = bg.w + SCALE*gc0.w; u = bu.w + SCALE*uc0.w; sg = 1.f/(1.f+__expf(-g)); h0.w = g*sg*u;
        g = bg.x + SCALE*gc1.x; u = bu.x + SCALE*uc1.x; sg = 1.f/(1.f+__expf(-g)); h1.x = g*sg*u;
        g = bg.y + SCALE*gc1.y; u = bu.y + SCALE*uc1.y; sg = 1.f/(1.f+__expf(-g)); h1.y = g*sg*u;
        g = bg.z + SCALE*gc1.z; u = bu.z + SCALE*uc1.z; sg = 1.f/(1.f+__expf(-g)); h1.z = g*sg*u;
        g = bg.w + SCALE*gc1.w; u = bu.w + SCALE*uc1.w; sg = 1.f/(1.f+__expf(-g)); h1.w = g*sg*u;
    }
    hm.x = f2tf32f(w0*h0.x + w1*h1.x); hm.y = f2tf32f(w0*h0.y + w1*h1.y);
    hm.z = f2tf32f(w0*h0.z + w1*h1.z); hm.w = f2tf32f(w0*h0.w + w1*h1.w);
    h0.x = f2tf32f(h0.x); h0.y = f2tf32f(h0.y); h0.z = f2tf32f(h0.z); h0.w = f2tf32f(h0.w);
    h1.x = f2tf32f(h1.x); h1.y = f2tf32f(h1.y); h1.z = f2tf32f(h1.z); h1.w = f2tf32f(h1.w);
    *(float4*)&g_hid01[idx] = h0;
    *(float4*)&g_hid01[o1]  = h1;
    *(float4*)&g_hmixext[(size_t)t * KDOWN + col] = hm;
}

// cvec tail columns of hmixext (tf32 output)
__global__ void cvec_kernel(){
    int idx = blockIdx.x * 256 + threadIdx.x;   // NTOK*EC
    int t = idx >> 9, j = idx & 511;
    int e = j >> 6;
    float v = 0.f;
    if (e == g_eids[2*t])   v += g_wts[2*t]   * g_corrall[(size_t)t * EC + j];
    if (e == g_eids[2*t+1]) v += g_wts[2*t+1] * g_corrall[(size_t)(NTOK + t) * EC + j];
    g_hmixext[(size_t)t * KDOWN + ID + j] = f2tf32f(SCALE * v);
}

// ---------------- launch ----------------
static void launch_gemm(const float* A, const float* B, float* C, int M, int N, int K){
    static bool attr_set = false;
    if (!attr_set){
        cudaFuncSetAttribute(gemm_tf32, cudaFuncAttributeMaxDynamicSharedMemorySize, SMEM_BYTES);
        attr_set = true;
    }
    dim3 grid(N / BN, M / BM);
    gemm_tf32<<<grid, 256, SMEM_BYTES>>>(A, B, C, M, N, K);
}

static void launch_conv(const float* in, float* out, size_t n){
    conv_kernel<<<(unsigned)((n / 4) / 256), 256>>>(in, out);
}

extern "C" void kernel_launch(void* const* d_in, const int* in_sizes, int n_in,
                              void* d_out, int out_size){
    const float* x      = (const float*)d_in[0];
    const float* conf_w = (const float*)d_in[1];
    const float* conf_b = (const float*)d_in[2];
    const float* wealth = (const float*)d_in[3];
    const float* bgw    = (const float*)d_in[4];
    const float* buw    = (const float*)d_in[5];
    const float* bdw    = (const float*)d_in[6];
    const float* gA     = (const float*)d_in[7];   // [512,2048]
    const float* gB     = (const float*)d_in[8];
    const float* uA     = (const float*)d_in[9];   // [512,2048]
    const float* uB     = (const float*)d_in[10];
    const float* dA     = (const float*)d_in[11];  // [512,7168]
    const float* dB     = (const float*)d_in[12];
    float* out = (float*)d_out;

    float *p_basegate, *p_baseup, *p_tg, *p_tu, *p_amg, *p_amu,
          *p_gBall, *p_uBall, *p_gc, *p_uc, *p_hid01, *p_hmixext,
          *p_corrall, *p_bcomb, *p_xc, *p_bgwc, *p_buwc, *p_gac, *p_uac, *p_dac;
    cudaGetSymbolAddress((void**)&p_basegate, g_basegate);
    cudaGetSymbolAddress((void**)&p_baseup,   g_baseup);
    cudaGetSymbolAddress((void**)&p_tg,       g_tg);
    cudaGetSymbolAddress((void**)&p_tu,       g_tu);
    cudaGetSymbolAddress((void**)&p_amg,      g_amg);
    cudaGetSymbolAddress((void**)&p_amu,      g_amu);
    cudaGetSymbolAddress((void**)&p_gBall,    g_gBall);
    cudaGetSymbolAddress((void**)&p_uBall,    g_uBall);
    cudaGetSymbolAddress((void**)&p_gc,       g_gc);
    cudaGetSymbolAddress((void**)&p_uc,       g_uc);
    cudaGetSymbolAddress((void**)&p_hid01,    g_hid01);
    cudaGetSymbolAddress((void**)&p_hmixext,  g_hmixext);
    cudaGetSymbolAddress((void**)&p_corrall,  g_corrall);
    cudaGetSymbolAddress((void**)&p_bcomb,    g_bcomb);
    cudaGetSymbolAddress((void**)&p_xc,       g_xc);
    cudaGetSymbolAddress((void**)&p_bgwc,     g_bgwc);
    cudaGetSymbolAddress((void**)&p_buwc,     g_buwc);
    cudaGetSymbolAddress((void**)&p_gac,      g_gac);
    cudaGetSymbolAddress((void**)&p_uac,      g_uac);
    cudaGetSymbolAddress((void**)&p_dac,      g_dac);

    routing_kernel<<<NTOK, 256>>>(x, conf_w, conf_b, wealth);

    // tf32 pre-conversion of GEMM operands
    launch_conv(x,   p_xc,   (size_t)NTOK*HD);
    launch_conv(bgw, p_bgwc, (size_t)ID*HD);
    launch_conv(buw, p_buwc, (size_t)ID*HD);
    launch_conv(gA,  p_gac,  (size_t)EC*HD);
    launch_conv(uA,  p_uac,  (size_t)EC*HD);
    launch_conv(dA,  p_dac,  (size_t)EC*ID);

    // packing (tf32 outputs)
    packB_kernel<<<(ID*EC)/256, 256>>>(gB, uB);
    bcomb_kernel<<<(HD*KDOWN)/256, 256>>>(bdw, dB);

    // base projections + LoRA-A (all experts stacked)
    launch_gemm(p_xc, p_bgwc, p_basegate, NTOK, ID, HD);
    launch_gemm(p_xc, p_buwc, p_baseup,   NTOK, ID, HD);
    launch_gemm(p_xc, p_gac,  p_tg, NTOK, EC, HD);
    launch_gemm(p_xc, p_uac,  p_tu, NTOK, EC, HD);

    // masked-dense LoRA-B expansion (slot-major M=4096)
    amask_kernel<<<(2*NTOK*EC)/256, 256>>>();
    launch_gemm(p_amg, p_gBall, p_gc, 2*NTOK, ID, EC);
    launch_gemm(p_amu, p_uBall, p_uc, 2*NTOK, ID, EC);

    // elementwise silu/mul + weighted mix
    hid_kernel<<<(NTOK*ID/4)/256, 256>>>();

    // down-LoRA correction via dense dA projection
    launch_gemm(p_hid01, p_dac, p_corrall, 2*NTOK, EC, ID);
    cvec_kernel<<<(NTOK*EC)/256, 256>>>();

    // fused down projection: out = [hmix | cvec] @ [bdw | dBall]^T
    launch_gemm(p_hmixext, p_bcomb, out, NTOK, HD, KDOWN);
}

// round 5
// speedup vs baseline: 3.6077x; 1.1476x over previous
#include <cuda_runtime.h>
#include <cstdint>
#include <math.h>

#define NTOK 2048
#define HD   2048
#define ID   7168
#define NE   8
#define NR   64
#define EC   (NE*NR)       // 512
#define KDOWN (ID+EC)      // 7680
#define NF   (2*ID+2*EC)   // 15360 fused x-side output width
#define SCALE 0.25f

// GEMM tiling: 128x128x32, 3 stages, 256 threads, 2 CTAs/SM
#define BM 128
#define BN 128
#define BK 32
#define STAGES 3
#define STAGE_FLOATS 8192           // A 4096 + B 4096
#define STAGE_BYTES  32768
#define SMEM_BYTES   (STAGES*STAGE_BYTES)   // 98304

// ---------------- scratch (__device__ globals) ----------------
__device__ float g_xc     [(size_t)NTOK*HD];
__device__ float g_fusedW [(size_t)NF*HD];        // [bgw|buw|gA|uA] tf32
__device__ float g_baseout[(size_t)NTOK*NF];      // [basegate|baseup|tg|tu]
__device__ float g_amg    [2*NTOK*EC];
__device__ float g_amu    [2*NTOK*EC];
__device__ float g_gBall  [(size_t)ID*EC];
__device__ float g_uBall  [(size_t)ID*EC];
__device__ float g_gc     [(size_t)2*NTOK*ID];
__device__ float g_uc     [(size_t)2*NTOK*ID];
__device__ float g_hid01  [(size_t)2*NTOK*ID];
__device__ float g_hmixext[(size_t)NTOK*KDOWN];
__device__ float g_corr0  [2*NTOK*EC];
__device__ float g_corr1  [2*NTOK*EC];
__device__ float g_bcomb  [(size_t)HD*KDOWN];
__device__ float g_dac    [(size_t)EC*ID];
__device__ int   g_eids   [2*NTOK];
__device__ float g_wts    [2*NTOK];

// ---------------- helpers ----------------
__device__ __forceinline__ float f2tf32f(float x){
    uint32_t r;
    asm("cvt.rna.tf32.f32 %0, %1;" : "=r"(r) : "f"(x));
    return __uint_as_float(r);
}

__device__ __forceinline__ void mma_tf32(float* c, const uint32_t* a, const uint32_t* b){
    asm volatile(
        "mma.sync.aligned.m16n8k8.row.col.f32.tf32.tf32.f32 "
        "{%0,%1,%2,%3}, {%4,%5,%6,%7}, {%8,%9}, {%0,%1,%2,%3};"
        : "+f"(c[0]), "+f"(c[1]), "+f"(c[2]), "+f"(c[3])
        : "r"(a[0]), "r"(a[1]), "r"(a[2]), "r"(a[3]), "r"(b[0]), "r"(b[1]));
}

__device__ __forceinline__ void cp16(uint32_t smaddr, const void* g){
    asm volatile("cp.async.cg.shared.global [%0], [%1], 16;"
                 :: "r"(smaddr), "l"(g));
}
__device__ __forceinline__ void cp_commit(){
    asm volatile("cp.async.commit_group;" ::: "memory");
}
template<int N> __device__ __forceinline__ void cp_wait(){
    asm volatile("cp.async.wait_group %0;" :: "n"(N) : "memory");
}

// ---------------- tf32 multistage GEMM: C[M,N] = A[M,K]*B[N,K]^T ----------------
// A,B tf32-preconverted. M%128==0, N%128==0, K%32==0. lda/ldb = row strides.
__global__ __launch_bounds__(256, 2) void gemm_tf32(
        const float* __restrict__ A, const float* __restrict__ B,
        float* __restrict__ C, int M, int N, int K, int lda, int ldb){
    extern __shared__ float sm[];
    const int tid = threadIdx.x;
    const int wid = tid >> 5, lane = tid & 31;
    const int wm = wid >> 2, wn = wid & 3;      // 2x4 warps, 64x32 tiles
    const int grp = lane >> 2, tig = lane & 3;
    const int m0 = blockIdx.y * BM, n0 = blockIdx.x * BN;

    uint32_t smem_base;
    {
        uint64_t t = __cvta_generic_to_shared(sm);
        smem_base = (uint32_t)t;
    }

    // --- cp.async mapping: 8x16B per thread per chunk ---
    const int rA = tid >> 3;             // 0..31
    const int cc = (tid & 7) << 2;
    const uint32_t ccs = (uint32_t)cc ^ (((uint32_t)(rA & 7)) << 2);
    const float* Agp = A + (size_t)(m0 + rA) * lda + cc;
    const float* Bgp = B + (size_t)(n0 + rA) * ldb + cc;
    const size_t rstepA = (size_t)32 * lda;
    const size_t rstepB = (size_t)32 * ldb;

    uint32_t dstA[4], dstB[4];
    #pragma unroll
    for (int q = 0; q < 4; q++){
        dstA[q] = ((uint32_t)(rA + 32*q) * 32u + ccs) * 4u;
        dstB[q] = 16384u + dstA[q];
    }

    const int nch = K >> 5;

    #pragma unroll
    for (int s = 0; s < STAGES-1; s++){
        if (s < nch){
            uint32_t base = smem_base + (uint32_t)s * STAGE_BYTES;
            const float* ag = Agp + (s << 5);
            const float* bg = Bgp + (s << 5);
            #pragma unroll
            for (int q = 0; q < 4; q++) cp16(base + dstA[q], ag + rstepA * q);
            #pragma unroll
            for (int q = 0; q < 4; q++) cp16(base + dstB[q], bg + rstepB * q);
        }
        cp_commit();
    }

    const uint32_t gx = (uint32_t)grp << 2;
    uint32_t aRow[4], bRow[4];
    #pragma unroll
    for (int i = 0; i < 4; i++) aRow[i] = (uint32_t)(wm*64 + i*16 + grp) * 32u;
    #pragma unroll
    for (int j = 0; j < 4; j++) bRow[j] = 4096u + (uint32_t)(wn*32 + j*8 + grp) * 32u;

    float acc[4][4][4];
    #pragma unroll
    for (int i = 0; i < 4; i++)
        #pragma unroll
        for (int j = 0; j < 4; j++)
            #pragma unroll
            for (int q = 0; q < 4; q++) acc[i][j][q] = 0.f;

    for (int c = 0; c < nch; c++){
        cp_wait<STAGES-2>();
        __syncthreads();

        if (c + STAGES-1 < nch){
            const int cn = c + STAGES-1;
            uint32_t base = smem_base + (uint32_t)(cn % STAGES) * STAGE_BYTES;
            const float* ag = Agp + (cn << 5);
            const float* bg = Bgp + (cn << 5);
            #pragma unroll
            for (int q = 0; q < 4; q++) cp16(base + dstA[q], ag + rstepA * q);
            #pragma unroll
            for (int q = 0; q < 4; q++) cp16(base + dstB[q], bg + rstepB * q);
        }
        cp_commit();

        const uint32_t* st = (const uint32_t*)(sm + (size_t)(c % STAGES) * STAGE_FLOATS);
        #pragma unroll
        for (int kk = 0; kk < 4; kk++){
            const uint32_t k0 = ((uint32_t)(kk*8) + tig) ^ gx;
            const uint32_t k1 = ((uint32_t)(kk*8) + tig + 4u) ^ gx;
            uint32_t af[4][4], bf[4][2];
            #pragma unroll
            for (int i = 0; i < 4; i++){
                af[i][0] = st[aRow[i] + k0];
                af[i][1] = st[aRow[i] + 256u + k0];
                af[i][2] = st[aRow[i] + k1];
                af[i][3] = st[aRow[i] + 256u + k1];
            }
            #pragma unroll
            for (int j = 0; j < 4; j++){
                bf[j][0] = st[bRow[j] + k0];
                bf[j][1] = st[bRow[j] + k1];
            }
            #pragma unroll
            for (int i = 0; i < 4; i++)
                #pragma unroll
                for (int j = 0; j < 4; j++)
                    mma_tf32(acc[i][j], af[i], bf[j]);
        }
    }

    #pragma unroll
    for (int i = 0; i < 4; i++){
        int r0 = m0 + wm*64 + i*16 + grp;
        float* cr0 = C + (size_t)r0 * N;
        float* cr1 = C + (size_t)(r0 + 8) * N;
        #pragma unroll
        for (int j = 0; j < 4; j++){
            int col = n0 + wn*32 + j*8 + (tig << 1);
            *(float2*)(cr0 + col) = make_float2(acc[i][j][0], acc[i][j][1]);
            *(float2*)(cr1 + col) = make_float2(acc[i][j][2], acc[i][j][3]);
        }
    }
}

// ---------------- tf32 conversion pass ----------------
__global__ void conv_kernel(const float* __restrict__ in, float* __restrict__ out){
    size_t i4 = ((size_t)blockIdx.x * 256 + threadIdx.x) << 2;
    float4 v = *(const float4*)(in + i4);
    v.x = f2tf32f(v.x); v.y = f2tf32f(v.y); v.z = f2tf32f(v.z); v.w = f2tf32f(v.w);
    *(float4*)(out + i4) = v;
}

// ---------------- routing ----------------
__global__ void routing_kernel(const float* __restrict__ x,
                               const float* __restrict__ cw,
                               const float* __restrict__ cb,
                               const float* __restrict__ wealth){
    int t = blockIdx.x;
    int w = threadIdx.x >> 5, lane = threadIdx.x & 31;
    const float* xr = x + (size_t)t * HD;
    const float* cr = cw + (size_t)w * HD;
    float s = 0.f;
    for (int j = lane; j < HD; j += 32) s += xr[j] * cr[j];
    #pragma unroll
    for (int o = 16; o; o >>= 1) s += __shfl_down_sync(0xffffffffu, s, o);
    __shared__ float bids[NE];
    if (lane == 0){
        float conf = 1.f / (1.f + expf(-(s + cb[w])));
        bids[w] = conf * wealth[w];
    }
    __syncthreads();
    if (threadIdx.x == 0){
        int e0 = 0; float b0 = bids[0];
        for (int e = 1; e < NE; e++) if (bids[e] > b0){ b0 = bids[e]; e0 = e; }
        int e1 = -1; float b1 = -1e30f;
        for (int e = 0; e < NE; e++) if (e != e0 && bids[e] > b1){ b1 = bids[e]; e1 = e; }
        float ed = expf(b1 - b0);
        float inv = 1.f / (1.f + ed);
        g_eids[2*t] = e0; g_eids[2*t+1] = e1;
        g_wts [2*t] = inv; g_wts [2*t+1] = ed * inv;
    }
}

// ---------------- masked LoRA-A scatter ----------------
__global__ void amask_kernel(){
    int idx = blockIdx.x * 256 + threadIdx.x;       // 2*NTOK*EC
    int row = idx >> 9, j = idx & 511;
    int k = row >> 11, t = row & 2047;
    int e = j >> 6;
    bool sel = (e == g_eids[2*t + k]);
    size_t tgoff = (size_t)t * NF + 2*ID + j;       // tg cols
    g_amg[idx] = sel ? f2tf32f(g_baseout[tgoff]) : 0.f;
    g_amu[idx] = sel ? f2tf32f(g_baseout[tgoff + EC]) : 0.f;
}

// gBall[i][e*64+r] = tf32(gB[e][i][r]); same for uBall
__global__ void packB_kernel(const float* __restrict__ gB, const float* __restrict__ uB){
    size_t idx = (size_t)blockIdx.x * 256 + threadIdx.x;  // ID*EC
    int i = (int)(idx >> 9); int j = (int)(idx & 511);
    int e = j >> 6, r = j & 63;
    size_t src = ((size_t)e * ID + i) * NR + r;
    g_gBall[idx] = f2tf32f(gB[src]);
    g_uBall[idx] = f2tf32f(uB[src]);
}

// bcomb[h][k] = tf32( bdw[h][k] (k<ID) else dB[e][h][r] )
__global__ void bcomb_kernel(const float* __restrict__ bdw, const float* __restrict__ dB){
    size_t idx = (size_t)blockIdx.x * 256 + threadIdx.x;  // HD*KDOWN
    int h = (int)(idx / KDOWN); int k = (int)(idx % KDOWN);
    float v;
    if (k < ID) v = bdw[(size_t)h * ID + k];
    else { int j = k - ID; int e = j >> 6; int r = j & 63;
           v = dB[((size_t)e * HD + h) * NR + r]; }
    g_bcomb[idx] = f2tf32f(v);
}

// hid elementwise: tf32 outputs
__global__ void hid_kernel(){
    size_t i4 = (size_t)blockIdx.x * 256 + threadIdx.x;   // NTOK*ID/4
    size_t idx = i4 << 2;
    int t = (int)(idx / ID); int col = (int)(idx % ID);
    float w0 = g_wts[2*t], w1 = g_wts[2*t+1];
    size_t boff = (size_t)t * NF + col;
    float4 bg = *(const float4*)&g_baseout[boff];
    float4 bu = *(const float4*)&g_baseout[boff + ID];
    size_t o1 = (size_t)(NTOK + t) * ID + col;
    float4 gc0 = *(const float4*)&g_gc[idx], gc1 = *(const float4*)&g_gc[o1];
    float4 uc0 = *(const float4*)&g_uc[idx], uc1 = *(const float4*)&g_uc[o1];
    float4 h0, h1, hm;
    {
        float g, u, sg;
        g = bg.x + SCALE*gc0.x; u = bu.x + SCALE*uc0.x; sg = 1.f/(1.f+__expf(-g)); h0.x = g*sg*u;
        g = bg.y + SCALE*gc0.y; u = bu.y + SCALE*uc0.y; sg = 1.f/(1.f+__expf(-g)); h0.y = g*sg*u;
        g = bg.z + SCALE*gc0.z; u = bu.z + SCALE*uc0.z; sg = 1.f/(1.f+__expf(-g)); h0.z = g*sg*u;
        g = bg.w + SCALE*gc0.w; u = bu.w + SCALE*uc0.w; sg = 1.f/(1.f+__expf(-g)); h0.w = g*sg*u;
        g = bg.x + SCALE*gc1.x; u = bu.x + SCALE*uc1.x; sg = 1.f/(1.f+__expf(-g)); h1.x = g*sg*u;
        g = bg.y + SCALE*gc1.y; u = bu.y + SCALE*uc1.y; sg = 1.f/(1.f+__expf(-g)); h1.y = g*sg*u;
        g = bg.z + SCALE*gc1.z; u = bu.z + SCALE*uc1.z; sg = 1.f/(1.f+__expf(-g)); h1.z = g*sg*u;
        g = bg.w + SCALE*gc1.w; u = bu.w + SCALE*uc1.w; sg = 1.f/(1.f+__expf(-g)); h1.w = g*sg*u;
    }
    hm.x = f2tf32f(w0*h0.x + w1*h1.x); hm.y = f2tf32f(w0*h0.y + w1*h1.y);
    hm.z = f2tf32f(w0*h0.z + w1*h1.z); hm.w = f2tf32f(w0*h0.w + w1*h1.w);
    h0.x = f2tf32f(h0.x); h0.y = f2tf32f(h0.y); h0.z = f2tf32f(h0.z); h0.w = f2tf32f(h0.w);
    h1.x = f2tf32f(h1.x); h1.y = f2tf32f(h1.y); h1.z = f2tf32f(h1.z); h1.w = f2tf32f(h1.w);
    *(float4*)&g_hid01[idx] = h0;
    *(float4*)&g_hid01[o1]  = h1;
    *(float4*)&g_hmixext[(size_t)t * KDOWN + col] = hm;
}

// cvec tail columns of hmixext; sums both split-K halves
__global__ void cvec_kernel(){
    int idx = blockIdx.x * 256 + threadIdx.x;   // NTOK*EC
    int t = idx >> 9, j = idx & 511;
    int e = j >> 6;
    float v = 0.f;
    if (e == g_eids[2*t]){
        size_t o = (size_t)t * EC + j;
        v += g_wts[2*t] * (g_corr0[o] + g_corr1[o]);
    }
    if (e == g_eids[2*t+1]){
        size_t o = (size_t)(NTOK + t) * EC + j;
        v += g_wts[2*t+1] * (g_corr0[o] + g_corr1[o]);
    }
    g_hmixext[(size_t)t * KDOWN + ID + j] = f2tf32f(SCALE * v);
}

// ---------------- launch ----------------
static void launch_gemm(const float* A, const float* B, float* C,
                        int M, int N, int K, int lda, int ldb){
    static bool attr_set = false;
    if (!attr_set){
        cudaFuncSetAttribute(gemm_tf32, cudaFuncAttributeMaxDynamicSharedMemorySize, SMEM_BYTES);
        attr_set = true;
    }
    dim3 grid(N / BN, M / BM);
    gemm_tf32<<<grid, 256, SMEM_BYTES>>>(A, B, C, M, N, K, lda, ldb);
}

static void launch_conv(const float* in, float* out, size_t n){
    conv_kernel<<<(unsigned)((n / 4) / 256), 256>>>(in, out);
}

extern "C" void kernel_launch(void* const* d_in, const int* in_sizes, int n_in,
                              void* d_out, int out_size){
    const float* x      = (const float*)d_in[0];
    const float* conf_w = (const float*)d_in[1];
    const float* conf_b = (const float*)d_in[2];
    const float* wealth = (const float*)d_in[3];
    const float* bgw    = (const float*)d_in[4];
    const float* buw    = (const float*)d_in[5];
    const float* bdw    = (const float*)d_in[6];
    const float* gA     = (const float*)d_in[7];   // [512,2048]
    const float* gB     = (const float*)d_in[8];
    const float* uA     = (const float*)d_in[9];   // [512,2048]
    const float* uB     = (const float*)d_in[10];
    const float* dA     = (const float*)d_in[11];  // [512,7168]
    const float* dB     = (const float*)d_in[12];
    float* out = (float*)d_out;

    float *p_xc, *p_fusedW, *p_baseout, *p_amg, *p_amu, *p_gBall, *p_uBall,
          *p_gc, *p_uc, *p_hid01, *p_hmixext, *p_corr0, *p_corr1, *p_bcomb, *p_dac;
    cudaGetSymbolAddress((void**)&p_xc,      g_xc);
    cudaGetSymbolAddress((void**)&p_fusedW,  g_fusedW);
    cudaGetSymbolAddress((void**)&p_baseout, g_baseout);
    cudaGetSymbolAddress((void**)&p_amg,     g_amg);
    cudaGetSymbolAddress((void**)&p_amu,     g_amu);
    cudaGetSymbolAddress((void**)&p_gBall,   g_gBall);
    cudaGetSymbolAddress((void**)&p_uBall,   g_uBall);
    cudaGetSymbolAddress((void**)&p_gc,      g_gc);
    cudaGetSymbolAddress((void**)&p_uc,      g_uc);
    cudaGetSymbolAddress((void**)&p_hid01,   g_hid01);
    cudaGetSymbolAddress((void**)&p_hmixext, g_hmixext);
    cudaGetSymbolAddress((void**)&p_corr0,   g_corr0);
    cudaGetSymbolAddress((void**)&p_corr1,   g_corr1);
    cudaGetSymbolAddress((void**)&p_bcomb,   g_bcomb);
    cudaGetSymbolAddress((void**)&p_dac,     g_dac);

    routing_kernel<<<NTOK, 256>>>(x, conf_w, conf_b, wealth);

    // tf32 pre-conversion; weights packed into one fused matrix
    launch_conv(x,   p_xc, (size_t)NTOK*HD);
    launch_conv(bgw, p_fusedW,                       (size_t)ID*HD);
    launch_conv(buw, p_fusedW + (size_t)ID*HD,       (size_t)ID*HD);
    launch_conv(gA,  p_fusedW + (size_t)2*ID*HD,     (size_t)EC*HD);
    launch_conv(uA,  p_fusedW + (size_t)(2*ID+EC)*HD,(size_t)EC*HD);
    launch_conv(dA,  p_dac, (size_t)EC*ID);

    packB_kernel<<<(ID*EC)/256, 256>>>(gB, uB);
    bcomb_kernel<<<(HD*KDOWN)/256, 256>>>(bdw, dB);

    // fused x-side GEMM: [basegate|baseup|tg|tu] = x @ fusedW^T
    launch_gemm(p_xc, p_fusedW, p_baseout, NTOK, NF, HD, HD, HD);

    // masked-dense LoRA-B expansion (slot-major M=4096)
    amask_kernel<<<(2*NTOK*EC)/256, 256>>>();
    launch_gemm(p_amg, p_gBall, p_gc, 2*NTOK, ID, EC, EC, EC);
    launch_gemm(p_amu, p_uBall, p_uc, 2*NTOK, ID, EC, EC, EC);

    // elementwise silu/mul + weighted mix
    hid_kernel<<<(NTOK*ID/4)/256, 256>>>();

    // down-LoRA correction: split-K in two independent halves
    launch_gemm(p_hid01,            p_dac,            p_corr0, 2*NTOK, EC, ID/2, ID, ID);
    launch_gemm(p_hid01 + ID/2,     p_dac + ID/2,     p_corr1, 2*NTOK, EC, ID/2, ID, ID);
    cvec_kernel<<<(NTOK*EC)/256, 256>>>();

    // fused down projection: out = [hmix | cvec] @ [bdw | dBall]^T
    launch_gemm(p_hmixext, p_bcomb, out, NTOK, HD, KDOWN, KDOWN, KDOWN);
}

// round 7
// speedup vs baseline: 4.1335x; 1.1458x over previous
#include <cuda_runtime.h>
#include <cstdint>
#include <math.h>

#define NTOK 2048
#define HD   2048
#define ID   7168
#define NE   8
#define NR   64
#define EC   (NE*NR)       // 512
#define KDOWN (ID+EC)      // 7680
#define NF   (2*ID+2*EC)   // 15360
#define SCALE 0.25f
#define NSLOT (2*NTOK)     // 4096
#define MAXTILE 40

// main GEMM tiling: 128x128x32, 3 stages
#define BM 128
#define BN 128
#define STAGES 3
#define STAGE_FLOATS 8192
#define STAGE_BYTES  32768
#define SMEM_BYTES   (STAGES*STAGE_BYTES)

// gateup kernel smem (PAD 68 rows)
#define GPAD 68
#define GU_MAT (128*GPAD)                  // floats per matrix
#define GU_SMEM_BYTES (4*GU_MAT*4)         // 139264

// corr kernel: 128x64x32, 3 stages
#define CK 1792                            // K per split (ID/4)
#define C_STAGE_FLOATS 6144                // A 4096 + B 2048
#define C_STAGE_BYTES 24576
#define C_SMEM_BYTES (3*C_STAGE_BYTES)     // 73728

// ---------------- scratch ----------------
__device__ float g_xc     [(size_t)NTOK*HD];
__device__ float g_fusedW [(size_t)NF*HD];
__device__ float g_baseout[(size_t)NTOK*NF];
__device__ float g_hs     [(size_t)NSLOT*ID];
__device__ float g_hmixext[(size_t)NTOK*KDOWN];
__device__ float g_corrp  [(size_t)4*NSLOT*NR];
__device__ float g_bcomb  [(size_t)HD*KDOWN];
__device__ float g_dac    [(size_t)EC*ID];
__device__ int   g_eids   [NSLOT];
__device__ float g_wts    [NSLOT];
__device__ int   g_cnt    [NE];
__device__ int   g_list   [NE*NSLOT];
__device__ int   g_tile_e [MAXTILE+8];
__device__ int   g_tile_base[MAXTILE+8];
__device__ int   g_ntiles;

// ---------------- helpers ----------------
__device__ __forceinline__ float f2tf32f(float x){
    uint32_t r;
    asm("cvt.rna.tf32.f32 %0, %1;" : "=r"(r) : "f"(x));
    return __uint_as_float(r);
}
__device__ __forceinline__ void mma_tf32(float* c, const uint32_t* a, const uint32_t* b){
    asm volatile(
        "mma.sync.aligned.m16n8k8.row.col.f32.tf32.tf32.f32 "
        "{%0,%1,%2,%3}, {%4,%5,%6,%7}, {%8,%9}, {%0,%1,%2,%3};"
        : "+f"(c[0]), "+f"(c[1]), "+f"(c[2]), "+f"(c[3])
        : "r"(a[0]), "r"(a[1]), "r"(a[2]), "r"(a[3]), "r"(b[0]), "r"(b[1]));
}
__device__ __forceinline__ void cp16(uint32_t smaddr, const void* g){
    asm volatile("cp.async.cg.shared.global [%0], [%1], 16;" :: "r"(smaddr), "l"(g));
}
__device__ __forceinline__ void cp16z(uint32_t smaddr, const void* g, uint32_t bytes){
    asm volatile("cp.async.cg.shared.global [%0], [%1], 16, %2;"
                 :: "r"(smaddr), "l"(g), "r"(bytes));
}
__device__ __forceinline__ void cp_commit(){
    asm volatile("cp.async.commit_group;" ::: "memory");
}
template<int N> __device__ __forceinline__ void cp_wait(){
    asm volatile("cp.async.wait_group %0;" :: "n"(N) : "memory");
}

// ---------------- main tf32 GEMM: C[M,N] = A[M,K]*B[N,K]^T ----------------
__global__ __launch_bounds__(256, 2) void gemm_tf32(
        const float* __restrict__ A, const float* __restrict__ B,
        float* __restrict__ C, int M, int N, int K, int lda, int ldb){
    extern __shared__ float sm[];
    const int tid = threadIdx.x;
    const int wid = tid >> 5, lane = tid & 31;
    const int wm = wid >> 2, wn = wid & 3;
    const int grp = lane >> 2, tig = lane & 3;
    const int m0 = blockIdx.y * BM, n0 = blockIdx.x * BN;
    uint32_t smem_base = (uint32_t)__cvta_generic_to_shared(sm);

    const int rA = tid >> 3;
    const int cc = (tid & 7) << 2;
    const uint32_t ccs = (uint32_t)cc ^ (((uint32_t)(rA & 7)) << 2);
    const float* Agp = A + (size_t)(m0 + rA) * lda + cc;
    const float* Bgp = B + (size_t)(n0 + rA) * ldb + cc;
    const size_t rstepA = (size_t)32 * lda;
    const size_t rstepB = (size_t)32 * ldb;

    uint32_t dstA[4], dstB[4];
    #pragma unroll
    for (int q = 0; q < 4; q++){
        dstA[q] = ((uint32_t)(rA + 32*q) * 32u + ccs) * 4u;
        dstB[q] = 16384u + dstA[q];
    }
    const int nch = K >> 5;

    #pragma unroll
    for (int s = 0; s < STAGES-1; s++){
        if (s < nch){
            uint32_t base = smem_base + (uint32_t)s * STAGE_BYTES;
            const float* ag = Agp + (s << 5);
            const float* bg = Bgp + (s << 5);
            #pragma unroll
            for (int q = 0; q < 4; q++) cp16(base + dstA[q], ag + rstepA * q);
            #pragma unroll
            for (int q = 0; q < 4; q++) cp16(base + dstB[q], bg + rstepB * q);
        }
        cp_commit();
    }

    const uint32_t gx = (uint32_t)grp << 2;
    uint32_t aRow[4], bRow[4];
    #pragma unroll
    for (int i = 0; i < 4; i++) aRow[i] = (uint32_t)(wm*64 + i*16 + grp) * 32u;
    #pragma unroll
    for (int j = 0; j < 4; j++) bRow[j] = 4096u + (uint32_t)(wn*32 + j*8 + grp) * 32u;

    float acc[4][4][4];
    #pragma unroll
    for (int i = 0; i < 4; i++)
        #pragma unroll
        for (int j = 0; j < 4; j++)
            #pragma unroll
            for (int q = 0; q < 4; q++) acc[i][j][q] = 0.f;

    for (int c = 0; c < nch; c++){
        cp_wait<STAGES-2>();
        __syncthreads();
        if (c + STAGES-1 < nch){
            const int cn = c + STAGES-1;
            uint32_t base = smem_base + (uint32_t)(cn % STAGES) * STAGE_BYTES;
            const float* ag = Agp + (cn << 5);
            const float* bg = Bgp + (cn << 5);
            #pragma unroll
            for (int q = 0; q < 4; q++) cp16(base + dstA[q], ag + rstepA * q);
            #pragma unroll
            for (int q = 0; q < 4; q++) cp16(base + dstB[q], bg + rstepB * q);
        }
        cp_commit();

        const uint32_t* st = (const uint32_t*)(sm + (size_t)(c % STAGES) * STAGE_FLOATS);
        #pragma unroll
        for (int kk = 0; kk < 4; kk++){
            const uint32_t k0 = ((uint32_t)(kk*8) + tig) ^ gx;
            const uint32_t k1 = ((uint32_t)(kk*8) + tig + 4u) ^ gx;
            uint32_t af[4][4], bf[4][2];
            #pragma unroll
            for (int i = 0; i < 4; i++){
                af[i][0] = st[aRow[i] + k0];
                af[i][1] = st[aRow[i] + 256u + k0];
                af[i][2] = st[aRow[i] + k1];
                af[i][3] = st[aRow[i] + 256u + k1];
            }
            #pragma unroll
            for (int j = 0; j < 4; j++){
                bf[j][0] = st[bRow[j] + k0];
                bf[j][1] = st[bRow[j] + k1];
            }
            #pragma unroll
            for (int i = 0; i < 4; i++)
                #pragma unroll
                for (int j = 0; j < 4; j++)
                    mma_tf32(acc[i][j], af[i], bf[j]);
        }
    }

    #pragma unroll
    for (int i = 0; i < 4; i++){
        int r0 = m0 + wm*64 + i*16 + grp;
        float* cr0 = C + (size_t)r0 * N;
        float* cr1 = C + (size_t)(r0 + 8) * N;
        #pragma unroll
        for (int j = 0; j < 4; j++){
            int col = n0 + wn*32 + j*8 + (tig << 1);
            *(float2*)(cr0 + col) = make_float2(acc[i][j][0], acc[i][j][1]);
            *(float2*)(cr1 + col) = make_float2(acc[i][j][2], acc[i][j][3]);
        }
    }
}

// ---------------- conv ----------------
__global__ void conv_kernel(const float* __restrict__ in, float* __restrict__ out){
    size_t i4 = ((size_t)blockIdx.x * 256 + threadIdx.x) << 2;
    float4 v = *(const float4*)(in + i4);
    v.x = f2tf32f(v.x); v.y = f2tf32f(v.y); v.z = f2tf32f(v.z); v.w = f2tf32f(v.w);
    *(float4*)(out + i4) = v;
}

// ---------------- routing + scatter ----------------
__global__ void zero_cnt_kernel(){ if (threadIdx.x < NE) g_cnt[threadIdx.x] = 0; }

__global__ void routing_kernel(const float* __restrict__ x,
                               const float* __restrict__ cw,
                               const float* __restrict__ cb,
                               const float* __restrict__ wealth){
    int t = blockIdx.x;
    int w = threadIdx.x >> 5, lane = threadIdx.x & 31;
    const float* xr = x + (size_t)t * HD;
    const float* cr = cw + (size_t)w * HD;
    float s = 0.f;
    for (int j = lane; j < HD; j += 32) s += xr[j] * cr[j];
    #pragma unroll
    for (int o = 16; o; o >>= 1) s += __shfl_down_sync(0xffffffffu, s, o);
    __shared__ float bids[NE];
    if (lane == 0){
        float conf = 1.f / (1.f + expf(-(s + cb[w])));
        bids[w] = conf * wealth[w];
    }
    __syncthreads();
    if (threadIdx.x == 0){
        int e0 = 0; float b0 = bids[0];
        for (int e = 1; e < NE; e++) if (bids[e] > b0){ b0 = bids[e]; e0 = e; }
        int e1 = -1; float b1 = -1e30f;
        for (int e = 0; e < NE; e++) if (e != e0 && bids[e] > b1){ b1 = bids[e]; e1 = e; }
        float ed = expf(b1 - b0);
        float inv = 1.f / (1.f + ed);
        g_eids[2*t] = e0; g_eids[2*t+1] = e1;
        g_wts [2*t] = inv; g_wts [2*t+1] = ed * inv;
        int p0 = atomicAdd(&g_cnt[e0], 1); g_list[e0*NSLOT + p0] = 2*t;
        int p1 = atomicAdd(&g_cnt[e1], 1); g_list[e1*NSLOT + p1] = 2*t + 1;
    }
}

__global__ void tilemeta_kernel(){
    if (threadIdx.x == 0){
        int nt = 0;
        for (int e = 0; e < NE; e++){
            int c = g_cnt[e];
            for (int b = 0; b < c; b += 128){
                g_tile_e[nt] = e; g_tile_base[nt] = b; nt++;
            }
        }
        g_ntiles = nt;
    }
}

// ---------------- fused gate/up kernel ----------------
// tile: 128 slots x 128 i-cols, K=64. hs[ent] = w_ent * silu(gate)*up, tf32-rounded.
__global__ __launch_bounds__(256, 1) void gateup_kernel(
        const float* __restrict__ gB, const float* __restrict__ uB){
    int tileid = blockIdx.y;
    if (tileid >= g_ntiles) return;
    const int e = g_tile_e[tileid];
    const int tbase = g_tile_base[tileid];
    const int cnt = g_cnt[e];
    const int i0 = blockIdx.x << 7;
    extern __shared__ float sm[];
    float* sAg = sm;
    float* sAu = sm + GU_MAT;
    float* sBg = sm + 2*GU_MAT;
    float* sBu = sm + 3*GU_MAT;
    __shared__ int s_ent[128];
    const int tid = threadIdx.x;
    if (tid < 128){
        int j = tbase + tid;
        s_ent[tid] = (j < cnt) ? g_list[e*NSLOT + j] : -1;
    }
    __syncthreads();

    // load: each thread handles (row = tid>>1, half = tid&1) for all 4 matrices
    {
        const int row = tid >> 1, half = tid & 1;
        const int koff = half << 5;
        int ent = s_ent[row];
        const float* srcg = g_baseout;
        if (ent >= 0){
            int t = ent >> 1;
            srcg = g_baseout + (size_t)t*NF + 2*ID + e*NR + koff;
        }
        float* dAg = sAg + row*GPAD + koff;
        float* dAu = sAu + row*GPAD + koff;
        #pragma unroll
        for (int q = 0; q < 8; q++){
            float4 vg = make_float4(0,0,0,0), vu = vg;
            if (ent >= 0){
                vg = *(const float4*)(srcg + q*4);
                vu = *(const float4*)(srcg + EC + q*4);
            }
            vg.x=f2tf32f(vg.x); vg.y=f2tf32f(vg.y); vg.z=f2tf32f(vg.z); vg.w=f2tf32f(vg.w);
            vu.x=f2tf32f(vu.x); vu.y=f2tf32f(vu.y); vu.z=f2tf32f(vu.z); vu.w=f2tf32f(vu.w);
            *(float4*)(dAg + q*4) = vg;
            *(float4*)(dAu + q*4) = vu;
        }
        const float* sbg = gB + ((size_t)e*ID + i0 + row)*NR + koff;
        const float* sbu = uB + ((size_t)e*ID + i0 + row)*NR + koff;
        float* dBg = sBg + row*GPAD + koff;
        float* dBu = sBu + row*GPAD + koff;
        #pragma unroll
        for (int q = 0; q < 8; q++){
            float4 vg = *(const float4*)(sbg + q*4);
            float4 vu = *(const float4*)(sbu + q*4);
            vg.x=f2tf32f(vg.x); vg.y=f2tf32f(vg.y); vg.z=f2tf32f(vg.z); vg.w=f2tf32f(vg.w);
            vu.x=f2tf32f(vu.x); vu.y=f2tf32f(vu.y); vu.z=f2tf32f(vu.z); vu.w=f2tf32f(vu.w);
            *(float4*)(dBg + q*4) = vg;
            *(float4*)(dBu + q*4) = vu;
        }
    }
    __syncthreads();

    const int wid = tid >> 5, lane = tid & 31;
    const int wm = wid >> 2, wn = wid & 3;
    const int grp = lane >> 2, tig = lane & 3;
    const uint32_t* uAg = (const uint32_t*)sAg;
    const uint32_t* uAu = (const uint32_t*)sAu;
    const uint32_t* uBg = (const uint32_t*)sBg;
    const uint32_t* uBu = (const uint32_t*)sBu;

    float accg[4][4][4], accu[4][4][4];
    #pragma unroll
    for (int i = 0; i < 4; i++)
        #pragma unroll
        for (int j = 0; j < 4; j++)
            #pragma unroll
            for (int q = 0; q < 4; q++){ accg[i][j][q]=0.f; accu[i][j][q]=0.f; }

    #pragma unroll
    for (int kk = 0; kk < 8; kk++){
        const int k0 = kk*8 + tig, k1 = k0 + 4;
        uint32_t ag[4][4], au[4][4], bg[4][2], bu[4][2];
        #pragma unroll
        for (int i = 0; i < 4; i++){
            int row = wm*64 + i*16 + grp;
            ag[i][0] = uAg[row*GPAD + k0];
            ag[i][1] = uAg[(row+8)*GPAD + k0];
            ag[i][2] = uAg[row*GPAD + k1];
            ag[i][3] = uAg[(row+8)*GPAD + k1];
            au[i][0] = uAu[row*GPAD + k0];
            au[i][1] = uAu[(row+8)*GPAD + k0];
            au[i][2] = uAu[row*GPAD + k1];
            au[i][3] = uAu[(row+8)*GPAD + k1];
        }
        #pragma unroll
        for (int j = 0; j < 4; j++){
            int rowb = wn*32 + j*8 + grp;
            bg[j][0] = uBg[rowb*GPAD + k0];
            bg[j][1] = uBg[rowb*GPAD + k1];
            bu[j][0] = uBu[rowb*GPAD + k0];
            bu[j][1] = uBu[rowb*GPAD + k1];
        }
        #pragma unroll
        for (int i = 0; i < 4; i++)
            #pragma unroll
            for (int j = 0; j < 4; j++){
                mma_tf32(accg[i][j], ag[i], bg[j]);
                mma_tf32(accu[i][j], au[i], bu[j]);
            }
    }

    // epilogue: base add + silu*up + weight, write hs
    #pragma unroll
    for (int i = 0; i < 4; i++){
        #pragma unroll
        for (int half = 0; half < 2; half++){
            int r = wm*64 + i*16 + grp + half*8;
            int ent = s_ent[r];
            if (ent < 0) continue;
            int t = ent >> 1;
            float w = g_wts[ent];
            const float* brow = g_baseout + (size_t)t*NF;
            float* hrow = g_hs + (size_t)ent*ID;
            #pragma unroll
            for (int j = 0; j < 4; j++){
                int col = i0 + wn*32 + j*8 + (tig << 1);
                float2 bg2 = *(const float2*)(brow + col);
                float2 bu2 = *(const float2*)(brow + ID + col);
                float cg0 = accg[i][j][half*2+0], cg1 = accg[i][j][half*2+1];
                float cu0 = accu[i][j][half*2+0], cu1 = accu[i][j][half*2+1];
                float gate0 = bg2.x + SCALE*cg0, gate1 = bg2.y + SCALE*cg1;
                float up0 = bu2.x + SCALE*cu0,  up1 = bu2.y + SCALE*cu1;
                float h0 = gate0 * (1.f/(1.f+__expf(-gate0))) * up0;
                float h1 = gate1 * (1.f/(1.f+__expf(-gate1))) * up1;
                *(float2*)(hrow + col) = make_float2(f2tf32f(w*h0), f2tf32f(w*h1));
            }
        }
    }
}

// ---------------- grouped corr GEMM: corrp[s][ent][r] = hs[ent][ks] . dac[e][r][ks] ----------------
// tile 128 slots x 64 r, K=CK per split, 128 threads (4 warps 2x2 of 64x32)
__global__ __launch_bounds__(128, 2) void corr_kernel(){
    int tileid = blockIdx.y;
    if (tileid >= g_ntiles) return;
    const int e = g_tile_e[tileid];
    const int tbase = g_tile_base[tileid];
    const int cnt = g_cnt[e];
    const int ks = blockIdx.x;
    extern __shared__ float sm[];
    __shared__ int s_ent[128];
    const int tid = threadIdx.x;
    if (tid < 128){
        int j = tbase + tid;
        s_ent[tid] = (j < cnt) ? g_list[e*NSLOT + j] : -1;
    }
    __syncthreads();
    uint32_t smem_base = (uint32_t)__cvta_generic_to_shared(sm);

    const int rA = tid >> 3;
    const int cc = (tid & 7) << 2;
    const uint32_t ccs = (uint32_t)cc ^ (((uint32_t)(rA & 7)) << 2);
    const size_t koff0 = (size_t)ks*CK + cc;

    const float* Asrc[8]; uint32_t Abytes[8];
    #pragma unroll
    for (int q = 0; q < 8; q++){
        int ent = s_ent[rA + 16*q];
        Asrc[q] = (ent >= 0) ? (g_hs + (size_t)ent*ID + koff0) : g_hs;
        Abytes[q] = (ent >= 0) ? 16u : 0u;
    }
    const float* Bsrc[4];
    #pragma unroll
    for (int q = 0; q < 4; q++)
        Bsrc[q] = g_dac + (size_t)(e*NR + rA + 16*q)*ID + koff0;

    uint32_t dstA[8], dstB[4];
    #pragma unroll
    for (int q = 0; q < 8; q++) dstA[q] = ((uint32_t)(rA + 16*q) * 32u + ccs) * 4u;
    #pragma unroll
    for (int q = 0; q < 4; q++) dstB[q] = 16384u + ((uint32_t)(rA + 16*q) * 32u + ccs) * 4u;

    const int nch = CK >> 5;   // 56

    #pragma unroll
    for (int s = 0; s < 2; s++){
        uint32_t base = smem_base + (uint32_t)s * C_STAGE_BYTES;
        #pragma unroll
        for (int q = 0; q < 8; q++) cp16z(base + dstA[q], Asrc[q] + (s<<5), Abytes[q]);
        #pragma unroll
        for (int q = 0; q < 4; q++) cp16(base + dstB[q], Bsrc[q] + (s<<5));
        cp_commit();
    }

    const int wid = tid >> 5, lane = tid & 31;
    const int wm = wid >> 1, wn = wid & 1;
    const int grp = lane >> 2, tig = lane & 3;
    const uint32_t gx = (uint32_t)grp << 2;
    uint32_t aRow[4], bRow[4];
    #pragma unroll
    for (int i = 0; i < 4; i++) aRow[i] = (uint32_t)(wm*64 + i*16 + grp) * 32u;
    #pragma unroll
    for (int j = 0; j < 4; j++) bRow[j] = 4096u + (uint32_t)(wn*32 + j*8 + grp) * 32u;

    float acc[4][4][4];
    #pragma unroll
    for (int i = 0; i < 4; i++)
        #pragma unroll
        for (int j = 0; j < 4; j++)
            #pragma unroll
            for (int q = 0; q < 4; q++) acc[i][j][q] = 0.f;

    for (int c = 0; c < nch; c++){
        cp_wait<1>();
        __syncthreads();
        if (c + 2 < nch){
            const int cn = c + 2;
            uint32_t base = smem_base + (uint32_t)(cn % 3) * C_STAGE_BYTES;
            #pragma unroll
            for (int q = 0; q < 8; q++) cp16z(base + dstA[q], Asrc[q] + (cn<<5), Abytes[q]);
            #pragma unroll
            for (int q = 0; q < 4; q++) cp16(base + dstB[q], Bsrc[q] + (cn<<5));
        }
        cp_commit();

        const uint32_t* st = (const uint32_t*)(sm + (size_t)(c % 3) * C_STAGE_FLOATS);
        #pragma unroll
        for (int kk = 0; kk < 4; kk++){
            const uint32_t k0 = ((uint32_t)(kk*8) + tig) ^ gx;
            const uint32_t k1 = ((uint32_t)(kk*8) + tig + 4u) ^ gx;
            uint32_t af[4][4], bf[4][2];
            #pragma unroll
            for (int i = 0; i < 4; i++){
                af[i][0] = st[aRow[i] + k0];
                af[i][1] = st[aRow[i] + 256u + k0];
                af[i][2] = st[aRow[i] + k1];
                af[i][3] = st[aRow[i] + 256u + k1];
            }
            #pragma unroll
            for (int j = 0; j < 4; j++){
                bf[j][0] = st[bRow[j] + k0];
                bf[j][1] = st[bRow[j] + k1];
            }
            #pragma unroll
            for (int i = 0; i < 4; i++)
                #pragma unroll
                for (int j = 0; j < 4; j++)
                    mma_tf32(acc[i][j], af[i], bf[j]);
        }
    }

    #pragma unroll
    for (int i = 0; i < 4; i++){
        #pragma unroll
        for (int half = 0; half < 2; half++){
            int r = wm*64 + i*16 + grp + half*8;
            int ent = s_ent[r];
            if (ent < 0) continue;
            float* crow = g_corrp + ((size_t)ks*NSLOT + ent)*NR;
            #pragma unroll
            for (int j = 0; j < 4; j++){
                int col = wn*32 + j*8 + (tig << 1);
                *(float2*)(crow + col) =
                    make_float2(acc[i][j][half*2+0], acc[i][j][half*2+1]);
            }
        }
    }
}

// ---------------- bcomb: [bdw | dB repack], tf32 ----------------
__global__ void bcomb_kernel(const float* __restrict__ bdw, const float* __restrict__ dB){
    size_t idx = (size_t)blockIdx.x * 256 + threadIdx.x;
    int h = (int)(idx / KDOWN); int k = (int)(idx % KDOWN);
    float v;
    if (k < ID) v = bdw[(size_t)h * ID + k];
    else { int j = k - ID; int e = j >> 6; int r = j & 63;
           v = dB[((size_t)e * HD + h) * NR + r]; }
    g_bcomb[idx] = f2tf32f(v);
}

// hmix head: hs0+hs1 (pre-weighted), tf32
__global__ void addhead_kernel(){
    size_t i4 = ((size_t)blockIdx.x * 256 + threadIdx.x) << 2;
    int t = (int)(i4 / ID); int col = (int)(i4 % ID);
    float4 a = *(const float4*)&g_hs[(size_t)(2*t)*ID + col];
    float4 b = *(const float4*)&g_hs[(size_t)(2*t+1)*ID + col];
    float4 o;
    o.x = f2tf32f(a.x+b.x); o.y = f2tf32f(a.y+b.y);
    o.z = f2tf32f(a.z+b.z); o.w = f2tf32f(a.w+b.w);
    *(float4*)&g_hmixext[(size_t)t * KDOWN + col] = o;
}

// cvec tail: sum splits (weights already in hs)
__global__ void cvec_kernel(){
    int idx = blockIdx.x * 256 + threadIdx.x;   // NTOK*EC
    int t = idx >> 9, j = idx & 511;
    int e = j >> 6, r = j & 63;
    float v = 0.f;
    #pragma unroll
    for (int k = 0; k < 2; k++){
        int ent = 2*t + k;
        if (g_eids[ent] == e){
            #pragma unroll
            for (int s = 0; s < 4; s++)
                v += g_corrp[((size_t)s*NSLOT + ent)*NR + r];
        }
    }
    g_hmixext[(size_t)t * KDOWN + ID + j] = f2tf32f(SCALE * v);
}

// ---------------- launch ----------------
static void launch_gemm(const float* A, const float* B, float* C,
                        int M, int N, int K, int lda, int ldb){
    dim3 grid(N / BN, M / BM);
    gemm_tf32<<<grid, 256, SMEM_BYTES>>>(A, B, C, M, N, K, lda, ldb);
}
static void launch_conv(const float* in, float* out, size_t n){
    conv_kernel<<<(unsigned)((n / 4) / 256), 256>>>(in, out);
}

extern "C" void kernel_launch(void* const* d_in, const int* in_sizes, int n_in,
                              void* d_out, int out_size){
    const float* x      = (const float*)d_in[0];
    const float* conf_w = (const float*)d_in[1];
    const float* conf_b = (const float*)d_in[2];
    const float* wealth = (const float*)d_in[3];
    const float* bgw    = (const float*)d_in[4];
    const float* buw    = (const float*)d_in[5];
    const float* bdw    = (const float*)d_in[6];
    const float* gA     = (const float*)d_in[7];
    const float* gB     = (const float*)d_in[8];
    const float* uA     = (const float*)d_in[9];
    const float* uB     = (const float*)d_in[10];
    const float* dA     = (const float*)d_in[11];
    const float* dB     = (const float*)d_in[12];
    float* out = (float*)d_out;

    static bool attr_set = false;
    if (!attr_set){
        cudaFuncSetAttribute(gemm_tf32, cudaFuncAttributeMaxDynamicSharedMemorySize, SMEM_BYTES);
        cudaFuncSetAttribute(gateup_kernel, cudaFuncAttributeMaxDynamicSharedMemorySize, GU_SMEM_BYTES);
        cudaFuncSetAttribute(corr_kernel, cudaFuncAttributeMaxDynamicSharedMemorySize, C_SMEM_BYTES);
        attr_set = true;
    }

    float *p_xc, *p_fusedW, *p_baseout, *p_hmixext;
    cudaGetSymbolAddress((void**)&p_xc,      g_xc);
    cudaGetSymbolAddress((void**)&p_fusedW,  g_fusedW);
    cudaGetSymbolAddress((void**)&p_baseout, g_baseout);
    cudaGetSymbolAddress((void**)&p_hmixext, g_hmixext);
    float *p_dac, *p_bcomb;
    cudaGetSymbolAddress((void**)&p_dac,     g_dac);
    cudaGetSymbolAddress((void**)&p_bcomb,   g_bcomb);

    zero_cnt_kernel<<<1, 32>>>();
    routing_kernel<<<NTOK, 256>>>(x, conf_w, conf_b, wealth);
    tilemeta_kernel<<<1, 32>>>();

    launch_conv(x,   p_xc, (size_t)NTOK*HD);
    launch_conv(bgw, p_fusedW,                        (size_t)ID*HD);
    launch_conv(buw, p_fusedW + (size_t)ID*HD,        (size_t)ID*HD);
    launch_conv(gA,  p_fusedW + (size_t)2*ID*HD,      (size_t)EC*HD);
    launch_conv(uA,  p_fusedW + (size_t)(2*ID+EC)*HD, (size_t)EC*HD);
    launch_conv(dA,  p_dac, (size_t)EC*ID);
    bcomb_kernel<<<((size_t)HD*KDOWN)/256, 256>>>(bdw, dB);

    // fused x-side GEMM: [basegate|baseup|tg|tu]
    launch_gemm(p_xc, p_fusedW, p_baseout, NTOK, NF, HD, HD, HD);

    // fused grouped gate/up (LoRA-B + silu + mix weight)
    gateup_kernel<<<dim3(ID/128, MAXTILE), 256, GU_SMEM_BYTES>>>(gB, uB);

    // hmix head
    addhead_kernel<<<(NTOK*ID/4)/256, 256>>>();

    // grouped down-LoRA correction, split-K 4
    corr_kernel<<<dim3(4, MAXTILE), 128, C_SMEM_BYTES>>>();
    cvec_kernel<<<(NTOK*EC)/256, 256>>>();

    // fused down projection
    launch_gemm(p_hmixext, p_bcomb, out, NTOK, HD, KDOWN, KDOWN, KDOWN);
}

// round 10
// speedup vs baseline: 4.3227x; 1.0458x over previous
#include <cuda_runtime.h>
#include <cstdint>
#include <math.h>

#define NTOK 2048
#define HD   2048
#define ID   7168
#define NE   8
#define NR   64
#define EC   (NE*NR)       // 512
#define KDOWN (ID+EC)      // 7680
#define NF   (2*ID+2*EC)   // 15360
#define SCALE 0.25f
#define NSLOT (2*NTOK)     // 4096
#define MAXTILE 40

// main GEMM tiling: 128x128x32, 3 stages, 128 threads (4 warps, 2x2 of 64x64)
#define BM 128
#define BN 128
#define STAGES 3
#define STAGE_FLOATS 8192
#define STAGE_BYTES  32768
#define SMEM_BYTES   (STAGES*STAGE_BYTES)

// gateup kernel smem (PAD 68 rows)
#define GPAD 68
#define GU_MAT (128*GPAD)
#define GU_SMEM_BYTES (4*GU_MAT*4)         // 139264

// corr kernel: 128x64x32, 3 stages
#define CK 1792
#define C_STAGE_FLOATS 6144
#define C_STAGE_BYTES 24576
#define C_SMEM_BYTES (3*C_STAGE_BYTES)

// ---------------- scratch ----------------
__device__ float g_xc     [(size_t)NTOK*HD];
__device__ float g_fusedW [(size_t)NF*HD];
__device__ float g_baseout[(size_t)NTOK*NF];
__device__ float g_hs     [(size_t)NSLOT*ID];
__device__ float g_hmixext[(size_t)NTOK*KDOWN];
__device__ float g_corrp  [(size_t)4*NSLOT*NR];
__device__ float g_bcomb  [(size_t)HD*KDOWN];
__device__ float g_dac    [(size_t)EC*ID];
__device__ int   g_eids   [NSLOT];
__device__ float g_wts    [NSLOT];
__device__ int   g_cnt    [NE];
__device__ int   g_list   [NE*NSLOT];
__device__ int   g_tile_e [MAXTILE+8];
__device__ int   g_tile_base[MAXTILE+8];
__device__ int   g_ntiles;

// ---------------- helpers ----------------
__device__ __forceinline__ float f2tf32f(float x){
    uint32_t r;
    asm("cvt.rna.tf32.f32 %0, %1;" : "=r"(r) : "f"(x));
    return __uint_as_float(r);
}
__device__ __forceinline__ void mma_tf32(float* c, const uint32_t* a, const uint32_t* b){
    asm volatile(
        "mma.sync.aligned.m16n8k8.row.col.f32.tf32.tf32.f32 "
        "{%0,%1,%2,%3}, {%4,%5,%6,%7}, {%8,%9}, {%0,%1,%2,%3};"
        : "+f"(c[0]), "+f"(c[1]), "+f"(c[2]), "+f"(c[3])
        : "r"(a[0]), "r"(a[1]), "r"(a[2]), "r"(a[3]), "r"(b[0]), "r"(b[1]));
}
__device__ __forceinline__ void cp16(uint32_t smaddr, const void* g){
    asm volatile("cp.async.cg.shared.global [%0], [%1], 16;" :: "r"(smaddr), "l"(g));
}
__device__ __forceinline__ void cp16z(uint32_t smaddr, const void* g, uint32_t bytes){
    asm volatile("cp.async.cg.shared.global [%0], [%1], 16, %2;"
                 :: "r"(smaddr), "l"(g), "r"(bytes));
}
__device__ __forceinline__ void cp_commit(){
    asm volatile("cp.async.commit_group;" ::: "memory");
}
template<int N> __device__ __forceinline__ void cp_wait(){
    asm volatile("cp.async.wait_group %0;" :: "n"(N) : "memory");
}

// ---------------- main tf32 GEMM: C[M,N] = A[M,K]*B[N,K]^T ----------------
// 128 threads: 4 warps in 2x2, each computing a 64x64 tile (32 MMA per k8).
__global__ __launch_bounds__(128, 2) void gemm_tf32(
        const float* __restrict__ A, const float* __restrict__ B,
        float* __restrict__ C, int M, int N, int K, int lda, int ldb){
    extern __shared__ float sm[];
    const int tid = threadIdx.x;
    const int wid = tid >> 5, lane = tid & 31;
    const int wm = wid >> 1, wn = wid & 1;
    const int grp = lane >> 2, tig = lane & 3;
    const int m0 = blockIdx.y * BM, n0 = blockIdx.x * BN;
    uint32_t smem_base = (uint32_t)__cvta_generic_to_shared(sm);

    // cp.async mapping: 128 threads, 16x16B per thread per chunk
    const int rA = tid >> 3;             // 0..15
    const int cc = (tid & 7) << 2;
    const uint32_t ccs = (uint32_t)cc ^ (((uint32_t)(rA & 7)) << 2);
    const float* Agp = A + (size_t)(m0 + rA) * lda + cc;
    const float* Bgp = B + (size_t)(n0 + rA) * ldb + cc;
    const size_t rstepA = (size_t)16 * lda;
    const size_t rstepB = (size_t)16 * ldb;

    uint32_t dstA[8], dstB[8];
    #pragma unroll
    for (int q = 0; q < 8; q++){
        dstA[q] = ((uint32_t)(rA + 16*q) * 32u + ccs) * 4u;
        dstB[q] = 16384u + dstA[q];
    }
    const int nch = K >> 5;

    #pragma unroll
    for (int s = 0; s < STAGES-1; s++){
        if (s < nch){
            uint32_t base = smem_base + (uint32_t)s * STAGE_BYTES;
            const float* ag = Agp + (s << 5);
            const float* bg = Bgp + (s << 5);
            #pragma unroll
            for (int q = 0; q < 8; q++) cp16(base + dstA[q], ag + rstepA * q);
            #pragma unroll
            for (int q = 0; q < 8; q++) cp16(base + dstB[q], bg + rstepB * q);
        }
        cp_commit();
    }

    const uint32_t gx = (uint32_t)grp << 2;
    uint32_t aRow[4], bRow[8];
    #pragma unroll
    for (int i = 0; i < 4; i++) aRow[i] = (uint32_t)(wm*64 + i*16 + grp) * 32u;
    #pragma unroll
    for (int j = 0; j < 8; j++) bRow[j] = 4096u + (uint32_t)(wn*64 + j*8 + grp) * 32u;

    float acc[4][8][4];
    #pragma unroll
    for (int i = 0; i < 4; i++)
        #pragma unroll
        for (int j = 0; j < 8; j++)
            #pragma unroll
            for (int q = 0; q < 4; q++) acc[i][j][q] = 0.f;

    for (int c = 0; c < nch; c++){
        cp_wait<STAGES-2>();
        __syncthreads();
        if (c + STAGES-1 < nch){
            const int cn = c + STAGES-1;
            uint32_t base = smem_base + (uint32_t)(cn % STAGES) * STAGE_BYTES;
            const float* ag = Agp + (cn << 5);
            const float* bg = Bgp + (cn << 5);
            #pragma unroll
            for (int q = 0; q < 8; q++) cp16(base + dstA[q], ag + rstepA * q);
            #pragma unroll
            for (int q = 0; q < 8; q++) cp16(base + dstB[q], bg + rstepB * q);
        }
        cp_commit();

        const uint32_t* st = (const uint32_t*)(sm + (size_t)(c % STAGES) * STAGE_FLOATS);
        #pragma unroll
        for (int kk = 0; kk < 4; kk++){
            const uint32_t k0 = ((uint32_t)(kk*8) + tig) ^ gx;
            const uint32_t k1 = ((uint32_t)(kk*8) + tig + 4u) ^ gx;
            uint32_t af[4][4], bf[8][2];
            #pragma unroll
            for (int i = 0; i < 4; i++){
                af[i][0] = st[aRow[i] + k0];
                af[i][1] = st[aRow[i] + 256u + k0];
                af[i][2] = st[aRow[i] + k1];
                af[i][3] = st[aRow[i] + 256u + k1];
            }
            #pragma unroll
            for (int j = 0; j < 8; j++){
                bf[j][0] = st[bRow[j] + k0];
                bf[j][1] = st[bRow[j] + k1];
            }
            #pragma unroll
            for (int i = 0; i < 4; i++)
                #pragma unroll
                for (int j = 0; j < 8; j++)
                    mma_tf32(acc[i][j], af[i], bf[j]);
        }
    }

    #pragma unroll
    for (int i = 0; i < 4; i++){
        int r0 = m0 + wm*64 + i*16 + grp;
        float* cr0 = C + (size_t)r0 * N;
        float* cr1 = C + (size_t)(r0 + 8) * N;
        #pragma unroll
        for (int j = 0; j < 8; j++){
            int col = n0 + wn*64 + j*8 + (tig << 1);
            *(float2*)(cr0 + col) = make_float2(acc[i][j][0], acc[i][j][1]);
            *(float2*)(cr1 + col) = make_float2(acc[i][j][2], acc[i][j][3]);
        }
    }
}

// ---------------- conv ----------------
__global__ void conv_kernel(const float* __restrict__ in, float* __restrict__ out){
    size_t i4 = ((size_t)blockIdx.x * 256 + threadIdx.x) << 2;
    float4 v = *(const float4*)(in + i4);
    v.x = f2tf32f(v.x); v.y = f2tf32f(v.y); v.z = f2tf32f(v.z); v.w = f2tf32f(v.w);
    *(float4*)(out + i4) = v;
}

// ---------------- routing + scatter ----------------
__global__ void zero_cnt_kernel(){ if (threadIdx.x < NE) g_cnt[threadIdx.x] = 0; }

__global__ void routing_kernel(const float* __restrict__ x,
                               const float* __restrict__ cw,
                               const float* __restrict__ cb,
                               const float* __restrict__ wealth){
    int t = blockIdx.x;
    int w = threadIdx.x >> 5, lane = threadIdx.x & 31;
    const float* xr = x + (size_t)t * HD;
    const float* cr = cw + (size_t)w * HD;
    float s = 0.f;
    for (int j = lane; j < HD; j += 32) s += xr[j] * cr[j];
    #pragma unroll
    for (int o = 16; o; o >>= 1) s += __shfl_down_sync(0xffffffffu, s, o);
    __shared__ float bids[NE];
    if (lane == 0){
        float conf = 1.f / (1.f + expf(-(s + cb[w])));
        bids[w] = conf * wealth[w];
    }
    __syncthreads();
    if (threadIdx.x == 0){
        int e0 = 0; float b0 = bids[0];
        for (int e = 1; e < NE; e++) if (bids[e] > b0){ b0 = bids[e]; e0 = e; }
        int e1 = -1; float b1 = -1e30f;
        for (int e = 0; e < NE; e++) if (e != e0 && bids[e] > b1){ b1 = bids[e]; e1 = e; }
        float ed = expf(b1 - b0);
        float inv = 1.f / (1.f + ed);
        g_eids[2*t] = e0; g_eids[2*t+1] = e1;
        g_wts [2*t] = inv; g_wts [2*t+1] = ed * inv;
        int p0 = atomicAdd(&g_cnt[e0], 1); g_list[e0*NSLOT + p0] = 2*t;
        int p1 = atomicAdd(&g_cnt[e1], 1); g_list[e1*NSLOT + p1] = 2*t + 1;
    }
}

__global__ void tilemeta_kernel(){
    if (threadIdx.x == 0){
        int nt = 0;
        for (int e = 0; e < NE; e++){
            int c = g_cnt[e];
            for (int b = 0; b < c; b += 128){
                g_tile_e[nt] = e; g_tile_base[nt] = b; nt++;
            }
        }
        g_ntiles = nt;
    }
}

// ---------------- fused gate/up kernel ----------------
__global__ __launch_bounds__(256, 1) void gateup_kernel(
        const float* __restrict__ gB, const float* __restrict__ uB){
    int tileid = blockIdx.y;
    if (tileid >= g_ntiles) return;
    const int e = g_tile_e[tileid];
    const int tbase = g_tile_base[tileid];
    const int cnt = g_cnt[e];
    const int i0 = blockIdx.x << 7;
    extern __shared__ float sm[];
    float* sAg = sm;
    float* sAu = sm + GU_MAT;
    float* sBg = sm + 2*GU_MAT;
    float* sBu = sm + 3*GU_MAT;
    __shared__ int s_ent[128];
    const int tid = threadIdx.x;
    if (tid < 128){
        int j = tbase + tid;
        s_ent[tid] = (j < cnt) ? g_list[e*NSLOT + j] : -1;
    }
    __syncthreads();

    {
        const int row = tid >> 1, half = tid & 1;
        const int koff = half << 5;
        int ent = s_ent[row];
        const float* srcg = g_baseout;
        if (ent >= 0){
            int t = ent >> 1;
            srcg = g_baseout + (size_t)t*NF + 2*ID + e*NR + koff;
        }
        float* dAg = sAg + row*GPAD + koff;
        float* dAu = sAu + row*GPAD + koff;
        #pragma unroll
        for (int q = 0; q < 8; q++){
            float4 vg = make_float4(0,0,0,0), vu = vg;
            if (ent >= 0){
                vg = *(const float4*)(srcg + q*4);
                vu = *(const float4*)(srcg + EC + q*4);
            }
            vg.x=f2tf32f(vg.x); vg.y=f2tf32f(vg.y); vg.z=f2tf32f(vg.z); vg.w=f2tf32f(vg.w);
            vu.x=f2tf32f(vu.x); vu.y=f2tf32f(vu.y); vu.z=f2tf32f(vu.z); vu.w=f2tf32f(vu.w);
            *(float4*)(dAg + q*4) = vg;
            *(float4*)(dAu + q*4) = vu;
        }
        const float* sbg = gB + ((size_t)e*ID + i0 + row)*NR + koff;
        const float* sbu = uB + ((size_t)e*ID + i0 + row)*NR + koff;
        float* dBg = sBg + row*GPAD + koff;
        float* dBu = sBu + row*GPAD + koff;
        #pragma unroll
        for (int q = 0; q < 8; q++){
            float4 vg = *(const float4*)(sbg + q*4);
            float4 vu = *(const float4*)(sbu + q*4);
            vg.x=f2tf32f(vg.x); vg.y=f2tf32f(vg.y); vg.z=f2tf32f(vg.z); vg.w=f2tf32f(vg.w);
            vu.x=f2tf32f(vu.x); vu.y=f2tf32f(vu.y); vu.z=f2tf32f(vu.z); vu.w=f2tf32f(vu.w);
            *(float4*)(dBg + q*4) = vg;
            *(float4*)(dBu + q*4) = vu;
        }
    }
    __syncthreads();

    const int wid = tid >> 5, lane = tid & 31;
    const int wm = wid >> 2, wn = wid & 3;
    const int grp = lane >> 2, tig = lane & 3;
    const uint32_t* uAg = (const uint32_t*)sAg;
    const uint32_t* uAu = (const uint32_t*)sAu;
    const uint32_t* uBg = (const uint32_t*)sBg;
    const uint32_t* uBu = (const uint32_t*)sBu;

    float accg[4][4][4], accu[4][4][4];
    #pragma unroll
    for (int i = 0; i < 4; i++)
        #pragma unroll
        for (int j = 0; j < 4; j++)
            #pragma unroll
            for (int q = 0; q < 4; q++){ accg[i][j][q]=0.f; accu[i][j][q]=0.f; }

    #pragma unroll
    for (int kk = 0; kk < 8; kk++){
        const int k0 = kk*8 + tig, k1 = k0 + 4;
        uint32_t ag[4][4], au[4][4], bg[4][2], bu[4][2];
        #pragma unroll
        for (int i = 0; i < 4; i++){
            int row = wm*64 + i*16 + grp;
            ag[i][0] = uAg[row*GPAD + k0];
            ag[i][1] = uAg[(row+8)*GPAD + k0];
            ag[i][2] = uAg[row*GPAD + k1];
            ag[i][3] = uAg[(row+8)*GPAD + k1];
            au[i][0] = uAu[row*GPAD + k0];
            au[i][1] = uAu[(row+8)*GPAD + k0];
            au[i][2] = uAu[row*GPAD + k1];
            au[i][3] = uAu[(row+8)*GPAD + k1];
        }
        #pragma unroll
        for (int j = 0; j < 4; j++){
            int rowb = wn*32 + j*8 + grp;
            bg[j][0] = uBg[rowb*GPAD + k0];
            bg[j][1] = uBg[rowb*GPAD + k1];
            bu[j][0] = uBu[rowb*GPAD + k0];
            bu[j][1] = uBu[rowb*GPAD + k1];
        }
        #pragma unroll
        for (int i = 0; i < 4; i++)
            #pragma unroll
            for (int j = 0; j < 4; j++){
                mma_tf32(accg[i][j], ag[i], bg[j]);
                mma_tf32(accu[i][j], au[i], bu[j]);
            }
    }

    #pragma unroll
    for (int i = 0; i < 4; i++){
        #pragma unroll
        for (int half = 0; half < 2; half++){
            int r = wm*64 + i*16 + grp + half*8;
            int ent = s_ent[r];
            if (ent < 0) continue;
            int t = ent >> 1;
            float w = g_wts[ent];
            const float* brow = g_baseout + (size_t)t*NF;
            float* hrow = g_hs + (size_t)ent*ID;
            #pragma unroll
            for (int j = 0; j < 4; j++){
                int col = i0 + wn*32 + j*8 + (tig << 1);
                float2 bg2 = *(const float2*)(brow + col);
                float2 bu2 = *(const float2*)(brow + ID + col);
                float cg0 = accg[i][j][half*2+0], cg1 = accg[i][j][half*2+1];
                float cu0 = accu[i][j][half*2+0], cu1 = accu[i][j][half*2+1];
                float gate0 = bg2.x + SCALE*cg0, gate1 = bg2.y + SCALE*cg1;
                float up0 = bu2.x + SCALE*cu0,  up1 = bu2.y + SCALE*cu1;
                float h0 = gate0 * (1.f/(1.f+__expf(-gate0))) * up0;
                float h1 = gate1 * (1.f/(1.f+__expf(-gate1))) * up1;
                *(float2*)(hrow + col) = make_float2(f2tf32f(w*h0), f2tf32f(w*h1));
            }
        }
    }
}

// ---------------- grouped corr GEMM ----------------
__global__ __launch_bounds__(128, 2) void corr_kernel(){
    int tileid = blockIdx.y;
    if (tileid >= g_ntiles) return;
    const int e = g_tile_e[tileid];
    const int tbase = g_tile_base[tileid];
    const int cnt = g_cnt[e];
    const int ks = blockIdx.x;
    extern __shared__ float sm[];
    __shared__ int s_ent[128];
    const int tid = threadIdx.x;
    if (tid < 128){
        int j = tbase + tid;
        s_ent[tid] = (j < cnt) ? g_list[e*NSLOT + j] : -1;
    }
    __syncthreads();
    uint32_t smem_base = (uint32_t)__cvta_generic_to_shared(sm);

    const int rA = tid >> 3;
    const int cc = (tid & 7) << 2;
    const uint32_t ccs = (uint32_t)cc ^ (((uint32_t)(rA & 7)) << 2);
    const size_t koff0 = (size_t)ks*CK + cc;

    const float* Asrc[8]; uint32_t Abytes[8];
    #pragma unroll
    for (int q = 0; q < 8; q++){
        int ent = s_ent[rA + 16*q];
        Asrc[q] = (ent >= 0) ? (g_hs + (size_t)ent*ID + koff0) : g_hs;
        Abytes[q] = (ent >= 0) ? 16u : 0u;
    }
    const float* Bsrc[4];
    #pragma unroll
    for (int q = 0; q < 4; q++)
        Bsrc[q] = g_dac + (size_t)(e*NR + rA + 16*q)*ID + koff0;

    uint32_t dstA[8], dstB[4];
    #pragma unroll
    for (int q = 0; q < 8; q++) dstA[q] = ((uint32_t)(rA + 16*q) * 32u + ccs) * 4u;
    #pragma unroll
    for (int q = 0; q < 4; q++) dstB[q] = 16384u + ((uint32_t)(rA + 16*q) * 32u + ccs) * 4u;

    const int nch = CK >> 5;

    #pragma unroll
    for (int s = 0; s < 2; s++){
        uint32_t base = smem_base + (uint32_t)s * C_STAGE_BYTES;
        #pragma unroll
        for (int q = 0; q < 8; q++) cp16z(base + dstA[q], Asrc[q] + (s<<5), Abytes[q]);
        #pragma unroll
        for (int q = 0; q < 4; q++) cp16(base + dstB[q], Bsrc[q] + (s<<5));
        cp_commit();
    }

    const int wid = tid >> 5, lane = tid & 31;
    const int wm = wid >> 1, wn = wid & 1;
    const int grp = lane >> 2, tig = lane & 3;
    const uint32_t gx = (uint32_t)grp << 2;
    uint32_t aRow[4], bRow[4];
    #pragma unroll
    for (int i = 0; i < 4; i++) aRow[i] = (uint32_t)(wm*64 + i*16 + grp) * 32u;
    #pragma unroll
    for (int j = 0; j < 4; j++) bRow[j] = 4096u + (uint32_t)(wn*32 + j*8 + grp) * 32u;

    float acc[4][4][4];
    #pragma unroll
    for (int i = 0; i < 4; i++)
        #pragma unroll
        for (int j = 0; j < 4; j++)
            #pragma unroll
            for (int q = 0; q < 4; q++) acc[i][j][q] = 0.f;

    for (int c = 0; c < nch; c++){
        cp_wait<1>();
        __syncthreads();
        if (c + 2 < nch){
            const int cn = c + 2;
            uint32_t base = smem_base + (uint32_t)(cn % 3) * C_STAGE_BYTES;
            #pragma unroll
            for (int q = 0; q < 8; q++) cp16z(base + dstA[q], Asrc[q] + (cn<<5), Abytes[q]);
            #pragma unroll
            for (int q = 0; q < 4; q++) cp16(base + dstB[q], Bsrc[q] + (cn<<5));
        }
        cp_commit();

        const uint32_t* st = (const uint32_t*)(sm + (size_t)(c % 3) * C_STAGE_FLOATS);
        #pragma unroll
        for (int kk = 0; kk < 4; kk++){
            const uint32_t k0 = ((uint32_t)(kk*8) + tig) ^ gx;
            const uint32_t k1 = ((uint32_t)(kk*8) + tig + 4u) ^ gx;
            uint32_t af[4][4], bf[4][2];
            #pragma unroll
            for (int i = 0; i < 4; i++){
                af[i][0] = st[aRow[i] + k0];
                af[i][1] = st[aRow[i] + 256u + k0];
                af[i][2] = st[aRow[i] + k1];
                af[i][3] = st[aRow[i] + 256u + k1];
            }
            #pragma unroll
            for (int j = 0; j < 4; j++){
                bf[j][0] = st[bRow[j] + k0];
                bf[j][1] = st[bRow[j] + k1];
            }
            #pragma unroll
            for (int i = 0; i < 4; i++)
                #pragma unroll
                for (int j = 0; j < 4; j++)
                    mma_tf32(acc[i][j], af[i], bf[j]);
        }
    }

    #pragma unroll
    for (int i = 0; i < 4; i++){
        #pragma unroll
        for (int half = 0; half < 2; half++){
            int r = wm*64 + i*16 + grp + half*8;
            int ent = s_ent[r];
            if (ent < 0) continue;
            float* crow = g_corrp + ((size_t)ks*NSLOT + ent)*NR;
            #pragma unroll
            for (int j = 0; j < 4; j++){
                int col = wn*32 + j*8 + (tig << 1);
                *(float2*)(crow + col) =
                    make_float2(acc[i][j][half*2+0], acc[i][j][half*2+1]);
            }
        }
    }
}

// ---------------- bcomb ----------------
__global__ void bcomb_kernel(const float* __restrict__ bdw, const float* __restrict__ dB){
    size_t idx = (size_t)blockIdx.x * 256 + threadIdx.x;
    int h = (int)(idx / KDOWN); int k = (int)(idx % KDOWN);
    float v;
    if (k < ID) v = bdw[(size_t)h * ID + k];
    else { int j = k - ID; int e = j >> 6; int r = j & 63;
           v = dB[((size_t)e * HD + h) * NR + r]; }
    g_bcomb[idx] = f2tf32f(v);
}

// hmix head: hs0+hs1
__global__ void addhead_kernel(){
    size_t i4 = ((size_t)blockIdx.x * 256 + threadIdx.x) << 2;
    int t = (int)(i4 / ID); int col = (int)(i4 % ID);
    float4 a = *(const float4*)&g_hs[(size_t)(2*t)*ID + col];
    float4 b = *(const float4*)&g_hs[(size_t)(2*t+1)*ID + col];
    float4 o;
    o.x = f2tf32f(a.x+b.x); o.y = f2tf32f(a.y+b.y);
    o.z = f2tf32f(a.z+b.z); o.w = f2tf32f(a.w+b.w);
    *(float4*)&g_hmixext[(size_t)t * KDOWN + col] = o;
}

// cvec tail
__global__ void cvec_kernel(){
    int idx = blockIdx.x * 256 + threadIdx.x;
    int t = idx >> 9, j = idx & 511;
    int e = j >> 6, r = j & 63;
    float v = 0.f;
    #pragma unroll
    for (int k = 0; k < 2; k++){
        int ent = 2*t + k;
        if (g_eids[ent] == e){
            #pragma unroll
            for (int s = 0; s < 4; s++)
                v += g_corrp[((size_t)s*NSLOT + ent)*NR + r];
        }
    }
    g_hmixext[(size_t)t * KDOWN + ID + j] = f2tf32f(SCALE * v);
}

// ---------------- launch ----------------
static void launch_gemm(const float* A, const float* B, float* C,
                        int M, int N, int K, int lda, int ldb){
    dim3 grid(N / BN, M / BM);
    gemm_tf32<<<grid, 128, SMEM_BYTES>>>(A, B, C, M, N, K, lda, ldb);
}
static void launch_conv(const float* in, float* out, size_t n){
    conv_kernel<<<(unsigned)((n / 4) / 256), 256>>>(in, out);
}

extern "C" void kernel_launch(void* const* d_in, const int* in_sizes, int n_in,
                              void* d_out, int out_size){
    const float* x      = (const float*)d_in[0];
    const float* conf_w = (const float*)d_in[1];
    const float* conf_b = (const float*)d_in[2];
    const float* wealth = (const float*)d_in[3];
    const float* bgw    = (const float*)d_in[4];
    const float* buw    = (const float*)d_in[5];
    const float* bdw    = (const float*)d_in[6];
    const float* gA     = (const float*)d_in[7];
    const float* gB     = (const float*)d_in[8];
    const float* uA     = (const float*)d_in[9];
    const float* uB     = (const float*)d_in[10];
    const float* dA     = (const float*)d_in[11];
    const float* dB     = (const float*)d_in[12];
    float* out = (float*)d_out;

    static bool attr_set = false;
    if (!attr_set){
        cudaFuncSetAttribute(gemm_tf32, cudaFuncAttributeMaxDynamicSharedMemorySize, SMEM_BYTES);
        cudaFuncSetAttribute(gateup_kernel, cudaFuncAttributeMaxDynamicSharedMemorySize, GU_SMEM_BYTES);
        cudaFuncSetAttribute(corr_kernel, cudaFuncAttributeMaxDynamicSharedMemorySize, C_SMEM_BYTES);
        attr_set = true;
    }

    float *p_xc, *p_fusedW, *p_baseout, *p_hmixext, *p_dac, *p_bcomb;
    cudaGetSymbolAddress((void**)&p_xc,      g_xc);
    cudaGetSymbolAddress((void**)&p_fusedW,  g_fusedW);
    cudaGetSymbolAddress((void**)&p_baseout, g_baseout);
    cudaGetSymbolAddress((void**)&p_hmixext, g_hmixext);
    cudaGetSymbolAddress((void**)&p_dac,     g_dac);
    cudaGetSymbolAddress((void**)&p_bcomb,   g_bcomb);

    zero_cnt_kernel<<<1, 32>>>();
    routing_kernel<<<NTOK, 256>>>(x, conf_w, conf_b, wealth);
    tilemeta_kernel<<<1, 32>>>();

    launch_conv(x,   p_xc, (size_t)NTOK*HD);
    launch_conv(bgw, p_fusedW,                        (size_t)ID*HD);
    launch_conv(buw, p_fusedW + (size_t)ID*HD,        (size_t)ID*HD);
    launch_conv(gA,  p_fusedW + (size_t)2*ID*HD,      (size_t)EC*HD);
    launch_conv(uA,  p_fusedW + (size_t)(2*ID+EC)*HD, (size_t)EC*HD);
    launch_conv(dA,  p_dac, (size_t)EC*ID);
    bcomb_kernel<<<((size_t)HD*KDOWN)/256, 256>>>(bdw, dB);

    // fused x-side GEMM
    launch_gemm(p_xc, p_fusedW, p_baseout, NTOK, NF, HD, HD, HD);

    // fused grouped gate/up
    gateup_kernel<<<dim3(ID/128, MAXTILE), 256, GU_SMEM_BYTES>>>(gB, uB);

    // hmix head
    addhead_kernel<<<(NTOK*ID/4)/256, 256>>>();

    // grouped down-LoRA correction, split-K 4
    corr_kernel<<<dim3(4, MAXTILE), 128, C_SMEM_BYTES>>>();
    cvec_kernel<<<(NTOK*EC)/256, 256>>>();

    // fused down projection
    launch_gemm(p_hmixext, p_bcomb, out, NTOK, HD, KDOWN, KDOWN, KDOWN);
}

// round 11
// speedup vs baseline: 4.4672x; 1.0334x over previous
#include <cuda_runtime.h>
#include <cstdint>
#include <math.h>

#define NTOK 2048
#define HD   2048
#define ID   7168
#define NE   8
#define NR   64
#define EC   (NE*NR)       // 512
#define KDOWN (ID+EC)      // 7680
#define NF   (2*ID+2*EC)   // 15360
#define SCALE 0.25f
#define NSLOT (2*NTOK)     // 4096
#define MAXTILE 40

// main GEMM tiling: 128x128x32, 3 stages, 128 threads (4 warps, 2x2 of 64x64)
#define BM 128
#define BN 128
#define STAGES 3
#define STAGE_FLOATS 8192
#define STAGE_BYTES  32768
#define SMEM_BYTES   (STAGES*STAGE_BYTES)

// gateup v2: 4 matrices x (2 chunks x 128 x 32 floats) = 128KB
#define GU_MATF 8192                       // floats per matrix
#define GU_SMEM_BYTES (4*GU_MATF*4)        // 131072

// corr kernel: 128x64x32, 3 stages
#define CK 1792
#define C_STAGE_FLOATS 6144
#define C_STAGE_BYTES 24576
#define C_SMEM_BYTES (3*C_STAGE_BYTES)

// ---------------- scratch ----------------
__device__ float g_xc     [(size_t)NTOK*HD];
__device__ float g_fusedW [(size_t)NF*HD];
__device__ float g_baseout[(size_t)NTOK*NF];
__device__ float g_hs     [(size_t)NSLOT*ID];
__device__ float g_hmixext[(size_t)NTOK*KDOWN];
__device__ float g_corrp  [(size_t)4*NSLOT*NR];
__device__ float g_bcomb  [(size_t)HD*KDOWN];
__device__ float g_dac    [(size_t)EC*ID];
__device__ float g_gBc    [(size_t)NE*ID*NR];
__device__ float g_uBc    [(size_t)NE*ID*NR];
__device__ int   g_eids   [NSLOT];
__device__ float g_wts    [NSLOT];
__device__ int   g_cnt    [NE];
__device__ int   g_list   [NE*NSLOT];
__device__ int   g_tile_e [MAXTILE+8];
__device__ int   g_tile_base[MAXTILE+8];
__device__ int   g_ntiles;

// ---------------- helpers ----------------
__device__ __forceinline__ float f2tf32f(float x){
    uint32_t r;
    asm("cvt.rna.tf32.f32 %0, %1;" : "=r"(r) : "f"(x));
    return __uint_as_float(r);
}
__device__ __forceinline__ void mma_tf32(float* c, const uint32_t* a, const uint32_t* b){
    asm volatile(
        "mma.sync.aligned.m16n8k8.row.col.f32.tf32.tf32.f32 "
        "{%0,%1,%2,%3}, {%4,%5,%6,%7}, {%8,%9}, {%0,%1,%2,%3};"
        : "+f"(c[0]), "+f"(c[1]), "+f"(c[2]), "+f"(c[3])
        : "r"(a[0]), "r"(a[1]), "r"(a[2]), "r"(a[3]), "r"(b[0]), "r"(b[1]));
}
__device__ __forceinline__ void cp16(uint32_t smaddr, const void* g){
    asm volatile("cp.async.cg.shared.global [%0], [%1], 16;" :: "r"(smaddr), "l"(g));
}
__device__ __forceinline__ void cp16z(uint32_t smaddr, const void* g, uint32_t bytes){
    asm volatile("cp.async.cg.shared.global [%0], [%1], 16, %2;"
                 :: "r"(smaddr), "l"(g), "r"(bytes));
}
__device__ __forceinline__ void cp_commit(){
    asm volatile("cp.async.commit_group;" ::: "memory");
}
template<int N> __device__ __forceinline__ void cp_wait(){
    asm volatile("cp.async.wait_group %0;" :: "n"(N) : "memory");
}

// ---------------- main tf32 GEMM: C[M,N] = A[M,K]*B[N,K]^T ----------------
// 128 threads: 4 warps in 2x2, each computing a 64x64 tile.
// Epilogue rounds columns >= roundN to tf32 (for operands feeding later GEMMs).
__global__ __launch_bounds__(128, 2) void gemm_tf32(
        const float* __restrict__ A, const float* __restrict__ B,
        float* __restrict__ C, int M, int N, int K, int lda, int ldb, int roundN){
    extern __shared__ float sm[];
    const int tid = threadIdx.x;
    const int wid = tid >> 5, lane = tid & 31;
    const int wm = wid >> 1, wn = wid & 1;
    const int grp = lane >> 2, tig = lane & 3;
    const int m0 = blockIdx.y * BM, n0 = blockIdx.x * BN;
    uint32_t smem_base = (uint32_t)__cvta_generic_to_shared(sm);

    const int rA = tid >> 3;
    const int cc = (tid & 7) << 2;
    const uint32_t ccs = (uint32_t)cc ^ (((uint32_t)(rA & 7)) << 2);
    const float* Agp = A + (size_t)(m0 + rA) * lda + cc;
    const float* Bgp = B + (size_t)(n0 + rA) * ldb + cc;
    const size_t rstepA = (size_t)16 * lda;
    const size_t rstepB = (size_t)16 * ldb;

    uint32_t dstA[8], dstB[8];
    #pragma unroll
    for (int q = 0; q < 8; q++){
        dstA[q] = ((uint32_t)(rA + 16*q) * 32u + ccs) * 4u;
        dstB[q] = 16384u + dstA[q];
    }
    const int nch = K >> 5;

    #pragma unroll
    for (int s = 0; s < STAGES-1; s++){
        if (s < nch){
            uint32_t base = smem_base + (uint32_t)s * STAGE_BYTES;
            const float* ag = Agp + (s << 5);
            const float* bg = Bgp + (s << 5);
            #pragma unroll
            for (int q = 0; q < 8; q++) cp16(base + dstA[q], ag + rstepA * q);
            #pragma unroll
            for (int q = 0; q < 8; q++) cp16(base + dstB[q], bg + rstepB * q);
        }
        cp_commit();
    }

    const uint32_t gx = (uint32_t)grp << 2;
    uint32_t aRow[4], bRow[8];
    #pragma unroll
    for (int i = 0; i < 4; i++) aRow[i] = (uint32_t)(wm*64 + i*16 + grp) * 32u;
    #pragma unroll
    for (int j = 0; j < 8; j++) bRow[j] = 4096u + (uint32_t)(wn*64 + j*8 + grp) * 32u;

    float acc[4][8][4];
    #pragma unroll
    for (int i = 0; i < 4; i++)
        #pragma unroll
        for (int j = 0; j < 8; j++)
            #pragma unroll
            for (int q = 0; q < 4; q++) acc[i][j][q] = 0.f;

    for (int c = 0; c < nch; c++){
        cp_wait<STAGES-2>();
        __syncthreads();
        if (c + STAGES-1 < nch){
            const int cn = c + STAGES-1;
            uint32_t base = smem_base + (uint32_t)(cn % STAGES) * STAGE_BYTES;
            const float* ag = Agp + (cn << 5);
            const float* bg = Bgp + (cn << 5);
            #pragma unroll
            for (int q = 0; q < 8; q++) cp16(base + dstA[q], ag + rstepA * q);
            #pragma unroll
            for (int q = 0; q < 8; q++) cp16(base + dstB[q], bg + rstepB * q);
        }
        cp_commit();

        const uint32_t* st = (const uint32_t*)(sm + (size_t)(c % STAGES) * STAGE_FLOATS);
        #pragma unroll
        for (int kk = 0; kk < 4; kk++){
            const uint32_t k0 = ((uint32_t)(kk*8) + tig) ^ gx;
            const uint32_t k1 = ((uint32_t)(kk*8) + tig + 4u) ^ gx;
            uint32_t af[4][4], bf[8][2];
            #pragma unroll
            for (int i = 0; i < 4; i++){
                af[i][0] = st[aRow[i] + k0];
                af[i][1] = st[aRow[i] + 256u + k0];
                af[i][2] = st[aRow[i] + k1];
                af[i][3] = st[aRow[i] + 256u + k1];
            }
            #pragma unroll
            for (int j = 0; j < 8; j++){
                bf[j][0] = st[bRow[j] + k0];
                bf[j][1] = st[bRow[j] + k1];
            }
            #pragma unroll
            for (int i = 0; i < 4; i++)
                #pragma unroll
                for (int j = 0; j < 8; j++)
                    mma_tf32(acc[i][j], af[i], bf[j]);
        }
    }

    #pragma unroll
    for (int i = 0; i < 4; i++){
        int r0 = m0 + wm*64 + i*16 + grp;
        float* cr0 = C + (size_t)r0 * N;
        float* cr1 = C + (size_t)(r0 + 8) * N;
        #pragma unroll
        for (int j = 0; j < 8; j++){
            int col = n0 + wn*64 + j*8 + (tig << 1);
            float v0 = acc[i][j][0], v1 = acc[i][j][1];
            float v2 = acc[i][j][2], v3 = acc[i][j][3];
            if (col >= roundN){
                v0 = f2tf32f(v0); v1 = f2tf32f(v1);
                v2 = f2tf32f(v2); v3 = f2tf32f(v3);
            }
            *(float2*)(cr0 + col) = make_float2(v0, v1);
            *(float2*)(cr1 + col) = make_float2(v2, v3);
        }
    }
}

// ---------------- conv ----------------
__global__ void conv_kernel(const float* __restrict__ in, float* __restrict__ out){
    size_t i4 = ((size_t)blockIdx.x * 256 + threadIdx.x) << 2;
    float4 v = *(const float4*)(in + i4);
    v.x = f2tf32f(v.x); v.y = f2tf32f(v.y); v.z = f2tf32f(v.z); v.w = f2tf32f(v.w);
    *(float4*)(out + i4) = v;
}

// ---------------- routing + scatter ----------------
__global__ void zero_cnt_kernel(){ if (threadIdx.x < NE) g_cnt[threadIdx.x] = 0; }

__global__ void routing_kernel(const float* __restrict__ x,
                               const float* __restrict__ cw,
                               const float* __restrict__ cb,
                               const float* __restrict__ wealth){
    int t = blockIdx.x;
    int w = threadIdx.x >> 5, lane = threadIdx.x & 31;
    const float* xr = x + (size_t)t * HD;
    const float* cr = cw + (size_t)w * HD;
    float s = 0.f;
    for (int j = lane; j < HD; j += 32) s += xr[j] * cr[j];
    #pragma unroll
    for (int o = 16; o; o >>= 1) s += __shfl_down_sync(0xffffffffu, s, o);
    __shared__ float bids[NE];
    if (lane == 0){
        float conf = 1.f / (1.f + expf(-(s + cb[w])));
        bids[w] = conf * wealth[w];
    }
    __syncthreads();
    if (threadIdx.x == 0){
        int e0 = 0; float b0 = bids[0];
        for (int e = 1; e < NE; e++) if (bids[e] > b0){ b0 = bids[e]; e0 = e; }
        int e1 = -1; float b1 = -1e30f;
        for (int e = 0; e < NE; e++) if (e != e0 && bids[e] > b1){ b1 = bids[e]; e1 = e; }
        float ed = expf(b1 - b0);
        float inv = 1.f / (1.f + ed);
        g_eids[2*t] = e0; g_eids[2*t+1] = e1;
        g_wts [2*t] = inv; g_wts [2*t+1] = ed * inv;
        int p0 = atomicAdd(&g_cnt[e0], 1); g_list[e0*NSLOT + p0] = 2*t;
        int p1 = atomicAdd(&g_cnt[e1], 1); g_list[e1*NSLOT + p1] = 2*t + 1;
    }
}

__global__ void tilemeta_kernel(){
    if (threadIdx.x == 0){
        int nt = 0;
        for (int e = 0; e < NE; e++){
            int c = g_cnt[e];
            for (int b = 0; b < c; b += 128){
                g_tile_e[nt] = e; g_tile_base[nt] = b; nt++;
            }
        }
        g_ntiles = nt;
    }
}

// ---------------- gateup v2: cp.async loads, swizzled chunk layout ----------------
// SMEM: 4 matrices [Ag|Au|Bg|Bu], each 2 chunks of [128 rows x 32 floats] swizzled.
// A = tg/tu rows gathered from baseout (pre-rounded tf32 by GEMM epilogue);
// B = gBc/uBc (pre-rounded). Output hs[ent] = w * silu(gate)*up.
__global__ __launch_bounds__(256, 1) void gateup_kernel(){
    int tileid = blockIdx.y;
    if (tileid >= g_ntiles) return;
    const int e = g_tile_e[tileid];
    const int tbase = g_tile_base[tileid];
    const int cnt = g_cnt[e];
    const int i0 = blockIdx.x << 7;
    extern __shared__ float sm[];
    __shared__ int s_ent[128];
    const int tid = threadIdx.x;
    if (tid < 128){
        int j = tbase + tid;
        s_ent[tid] = (j < cnt) ? g_list[e*NSLOT + j] : -1;
    }
    __syncthreads();
    uint32_t smem_base = (uint32_t)__cvta_generic_to_shared(sm);

    // load: 256 threads x 32 cp16 (4 rows-q x 2 chunks x 4 matrices)
    {
        const int rA = tid >> 3;             // 0..31
        const int cc = (tid & 7) << 2;
        const uint32_t ccs = (uint32_t)cc ^ (((uint32_t)(rA & 7)) << 2);
        #pragma unroll
        for (int q = 0; q < 4; q++){
            const int row = rA + 32*q;
            const int ent = s_ent[row];
            const int t = ent >> 1;
            const uint32_t abytes = (ent >= 0) ? 16u : 0u;
            const float* asrc = (ent >= 0)
                ? (g_baseout + (size_t)t*NF + 2*ID + e*NR)
                : g_baseout;
            const float* bsrcg = g_gBc + ((size_t)e*ID + i0 + row)*NR;
            const float* bsrcu = g_uBc + ((size_t)e*ID + i0 + row)*NR;
            #pragma unroll
            for (int ch = 0; ch < 2; ch++){
                const uint32_t dst = ((uint32_t)ch*4096u + (uint32_t)row*32u + ccs)*4u;
                const int kof = ch*32 + cc;
                cp16z(smem_base + dst,                 asrc + kof,      abytes);  // Ag
                cp16z(smem_base + 32768u + dst,        asrc + EC + kof, abytes);  // Au
                cp16 (smem_base + 65536u + dst,        bsrcg + kof);              // Bg
                cp16 (smem_base + 98304u + dst,        bsrcu + kof);              // Bu
            }
        }
        cp_commit();
    }
    cp_wait<0>();
    __syncthreads();

    const int wid = tid >> 5, lane = tid & 31;
    const int wm = wid >> 2, wn = wid & 3;      // 2x4 warps, 64x32 tiles
    const int grp = lane >> 2, tig = lane & 3;
    const uint32_t gx = (uint32_t)grp << 2;
    const uint32_t* uAg = (const uint32_t*)sm;
    const uint32_t* uAu = (const uint32_t*)(sm + GU_MATF);
    const uint32_t* uBg = (const uint32_t*)(sm + 2*GU_MATF);
    const uint32_t* uBu = (const uint32_t*)(sm + 3*GU_MATF);

    uint32_t aRow[4], bRow[4];
    #pragma unroll
    for (int i = 0; i < 4; i++) aRow[i] = (uint32_t)(wm*64 + i*16 + grp) * 32u;
    #pragma unroll
    for (int j = 0; j < 4; j++) bRow[j] = (uint32_t)(wn*32 + j*8 + grp) * 32u;

    float accg[4][4][4], accu[4][4][4];
    #pragma unroll
    for (int i = 0; i < 4; i++)
        #pragma unroll
        for (int j = 0; j < 4; j++)
            #pragma unroll
            for (int q = 0; q < 4; q++){ accg[i][j][q]=0.f; accu[i][j][q]=0.f; }

    #pragma unroll
    for (int ch = 0; ch < 2; ch++){
        const uint32_t cb = (uint32_t)ch * 4096u;
        #pragma unroll
        for (int kk = 0; kk < 4; kk++){
            const uint32_t k0 = ((uint32_t)(kk*8) + tig) ^ gx;
            const uint32_t k1 = ((uint32_t)(kk*8) + tig + 4u) ^ gx;
            uint32_t ag[4][4], au[4][4], bg[4][2], bu[4][2];
            #pragma unroll
            for (int i = 0; i < 4; i++){
                ag[i][0] = uAg[cb + aRow[i] + k0];
                ag[i][1] = uAg[cb + aRow[i] + 256u + k0];
                ag[i][2] = uAg[cb + aRow[i] + k1];
                ag[i][3] = uAg[cb + aRow[i] + 256u + k1];
                au[i][0] = uAu[cb + aRow[i] + k0];
                au[i][1] = uAu[cb + aRow[i] + 256u + k0];
                au[i][2] = uAu[cb + aRow[i] + k1];
                au[i][3] = uAu[cb + aRow[i] + 256u + k1];
            }
            #pragma unroll
            for (int j = 0; j < 4; j++){
                bg[j][0] = uBg[cb + bRow[j] + k0];
                bg[j][1] = uBg[cb + bRow[j] + k1];
                bu[j][0] = uBu[cb + bRow[j] + k0];
                bu[j][1] = uBu[cb + bRow[j] + k1];
            }
            #pragma unroll
            for (int i = 0; i < 4; i++)
                #pragma unroll
                for (int j = 0; j < 4; j++){
                    mma_tf32(accg[i][j], ag[i], bg[j]);
                    mma_tf32(accu[i][j], au[i], bu[j]);
                }
        }
    }

    // epilogue: base add + silu*up + weight, write hs
    #pragma unroll
    for (int i = 0; i < 4; i++){
        #pragma unroll
        for (int half = 0; half < 2; half++){
            int r = wm*64 + i*16 + grp + half*8;
            int ent = s_ent[r];
            if (ent < 0) continue;
            int t = ent >> 1;
            float w = g_wts[ent];
            const float* brow = g_baseout + (size_t)t*NF;
            float* hrow = g_hs + (size_t)ent*ID;
            #pragma unroll
            for (int j = 0; j < 4; j++){
                int col = i0 + wn*32 + j*8 + (tig << 1);
                float2 bg2 = *(const float2*)(brow + col);
                float2 bu2 = *(const float2*)(brow + ID + col);
                float cg0 = accg[i][j][half*2+0], cg1 = accg[i][j][half*2+1];
                float cu0 = accu[i][j][half*2+0], cu1 = accu[i][j][half*2+1];
                float gate0 = bg2.x + SCALE*cg0, gate1 = bg2.y + SCALE*cg1;
                float up0 = bu2.x + SCALE*cu0,  up1 = bu2.y + SCALE*cu1;
                float h0 = gate0 * (1.f/(1.f+__expf(-gate0))) * up0;
                float h1 = gate1 * (1.f/(1.f+__expf(-gate1))) * up1;
                *(float2*)(hrow + col) = make_float2(f2tf32f(w*h0), f2tf32f(w*h1));
            }
        }
    }
}

// ---------------- grouped corr GEMM ----------------
__global__ __launch_bounds__(128, 2) void corr_kernel(){
    int tileid = blockIdx.y;
    if (tileid >= g_ntiles) return;
    const int e = g_tile_e[tileid];
    const int tbase = g_tile_base[tileid];
    const int cnt = g_cnt[e];
    const int ks = blockIdx.x;
    extern __shared__ float sm[];
    __shared__ int s_ent[128];
    const int tid = threadIdx.x;
    if (tid < 128){
        int j = tbase + tid;
        s_ent[tid] = (j < cnt) ? g_list[e*NSLOT + j] : -1;
    }
    __syncthreads();
    uint32_t smem_base = (uint32_t)__cvta_generic_to_shared(sm);

    const int rA = tid >> 3;
    const int cc = (tid & 7) << 2;
    const uint32_t ccs = (uint32_t)cc ^ (((uint32_t)(rA & 7)) << 2);
    const size_t koff0 = (size_t)ks*CK + cc;

    const float* Asrc[8]; uint32_t Abytes[8];
    #pragma unroll
    for (int q = 0; q < 8; q++){
        int ent = s_ent[rA + 16*q];
        Asrc[q] = (ent >= 0) ? (g_hs + (size_t)ent*ID + koff0) : g_hs;
        Abytes[q] = (ent >= 0) ? 16u : 0u;
    }
    const float* Bsrc[4];
    #pragma unroll
    for (int q = 0; q < 4; q++)
        Bsrc[q] = g_dac + (size_t)(e*NR + rA + 16*q)*ID + koff0;

    uint32_t dstA[8], dstB[4];
    #pragma unroll
    for (int q = 0; q < 8; q++) dstA[q] = ((uint32_t)(rA + 16*q) * 32u + ccs) * 4u;
    #pragma unroll
    for (int q = 0; q < 4; q++) dstB[q] = 16384u + ((uint32_t)(rA + 16*q) * 32u + ccs) * 4u;

    const int nch = CK >> 5;

    #pragma unroll
    for (int s = 0; s < 2; s++){
        uint32_t base = smem_base + (uint32_t)s * C_STAGE_BYTES;
        #pragma unroll
        for (int q = 0; q < 8; q++) cp16z(base + dstA[q], Asrc[q] + (s<<5), Abytes[q]);
        #pragma unroll
        for (int q = 0; q < 4; q++) cp16(base + dstB[q], Bsrc[q] + (s<<5));
        cp_commit();
    }

    const int wid = tid >> 5, lane = tid & 31;
    const int wm = wid >> 1, wn = wid & 1;
    const int grp = lane >> 2, tig = lane & 3;
    const uint32_t gx = (uint32_t)grp << 2;
    uint32_t aRow[4], bRow[4];
    #pragma unroll
    for (int i = 0; i < 4; i++) aRow[i] = (uint32_t)(wm*64 + i*16 + grp) * 32u;
    #pragma unroll
    for (int j = 0; j < 4; j++) bRow[j] = 4096u + (uint32_t)(wn*32 + j*8 + grp) * 32u;

    float acc[4][4][4];
    #pragma unroll
    for (int i = 0; i < 4; i++)
        #pragma unroll
        for (int j = 0; j < 4; j++)
            #pragma unroll
            for (int q = 0; q < 4; q++) acc[i][j][q] = 0.f;

    for (int c = 0; c < nch; c++){
        cp_wait<1>();
        __syncthreads();
        if (c + 2 < nch){
            const int cn = c + 2;
            uint32_t base = smem_base + (uint32_t)(cn % 3) * C_STAGE_BYTES;
            #pragma unroll
            for (int q = 0; q < 8; q++) cp16z(base + dstA[q], Asrc[q] + (cn<<5), Abytes[q]);
            #pragma unroll
            for (int q = 0; q < 4; q++) cp16(base + dstB[q], Bsrc[q] + (cn<<5));
        }
        cp_commit();

        const uint32_t* st = (const uint32_t*)(sm + (size_t)(c % 3) * C_STAGE_FLOATS);
        #pragma unroll
        for (int kk = 0; kk < 4; kk++){
            const uint32_t k0 = ((uint32_t)(kk*8) + tig) ^ gx;
            const uint32_t k1 = ((uint32_t)(kk*8) + tig + 4u) ^ gx;
            uint32_t af[4][4], bf[4][2];
            #pragma unroll
            for (int i = 0; i < 4; i++){
                af[i][0] = st[aRow[i] + k0];
                af[i][1] = st[aRow[i] + 256u + k0];
                af[i][2] = st[aRow[i] + k1];
                af[i][3] = st[aRow[i] + 256u + k1];
            }
            #pragma unroll
            for (int j = 0; j < 4; j++){
                bf[j][0] = st[bRow[j] + k0];
                bf[j][1] = st[bRow[j] + k1];
            }
            #pragma unroll
            for (int i = 0; i < 4; i++)
                #pragma unroll
                for (int j = 0; j < 4; j++)
                    mma_tf32(acc[i][j], af[i], bf[j]);
        }
    }

    #pragma unroll
    for (int i = 0; i < 4; i++){
        #pragma unroll
        for (int half = 0; half < 2; half++){
            int r = wm*64 + i*16 + grp + half*8;
            int ent = s_ent[r];
            if (ent < 0) continue;
            float* crow = g_corrp + ((size_t)ks*NSLOT + ent)*NR;
            #pragma unroll
            for (int j = 0; j < 4; j++){
                int col = wn*32 + j*8 + (tig << 1);
                *(float2*)(crow + col) =
                    make_float2(acc[i][j][half*2+0], acc[i][j][half*2+1]);
            }
        }
    }
}

// ---------------- bcomb ----------------
__global__ void bcomb_kernel(const float* __restrict__ bdw, const float* __restrict__ dB){
    size_t idx = (size_t)blockIdx.x * 256 + threadIdx.x;
    int h = (int)(idx / KDOWN); int k = (int)(idx % KDOWN);
    float v;
    if (k < ID) v = bdw[(size_t)h * ID + k];
    else { int j = k - ID; int e = j >> 6; int r = j & 63;
           v = dB[((size_t)e * HD + h) * NR + r]; }
    g_bcomb[idx] = f2tf32f(v);
}

// hmix head: hs0+hs1
__global__ void addhead_kernel(){
    size_t i4 = ((size_t)blockIdx.x * 256 + threadIdx.x) << 2;
    int t = (int)(i4 / ID); int col = (int)(i4 % ID);
    float4 a = *(const float4*)&g_hs[(size_t)(2*t)*ID + col];
    float4 b = *(const float4*)&g_hs[(size_t)(2*t+1)*ID + col];
    float4 o;
    o.x = f2tf32f(a.x+b.x); o.y = f2tf32f(a.y+b.y);
    o.z = f2tf32f(a.z+b.z); o.w = f2tf32f(a.w+b.w);
    *(float4*)&g_hmixext[(size_t)t * KDOWN + col] = o;
}

// cvec tail
__global__ void cvec_kernel(){
    int idx = blockIdx.x * 256 + threadIdx.x;
    int t = idx >> 9, j = idx & 511;
    int e = j >> 6, r = j & 63;
    float v = 0.f;
    #pragma unroll
    for (int k = 0; k < 2; k++){
        int ent = 2*t + k;
        if (g_eids[ent] == e){
            #pragma unroll
            for (int s = 0; s < 4; s++)
                v += g_corrp[((size_t)s*NSLOT + ent)*NR + r];
        }
    }
    g_hmixext[(size_t)t * KDOWN + ID + j] = f2tf32f(SCALE * v);
}

// ---------------- launch ----------------
static void launch_gemm(const float* A, const float* B, float* C,
                        int M, int N, int K, int lda, int ldb, int roundN){
    dim3 grid(N / BN, M / BM);
    gemm_tf32<<<grid, 128, SMEM_BYTES>>>(A, B, C, M, N, K, lda, ldb, roundN);
}
static void launch_conv(const float* in, float* out, size_t n){
    conv_kernel<<<(unsigned)((n / 4) / 256), 256>>>(in, out);
}

extern "C" void kernel_launch(void* const* d_in, const int* in_sizes, int n_in,
                              void* d_out, int out_size){
    const float* x      = (const float*)d_in[0];
    const float* conf_w = (const float*)d_in[1];
    const float* conf_b = (const float*)d_in[2];
    const float* wealth = (const float*)d_in[3];
    const float* bgw    = (const float*)d_in[4];
    const float* buw    = (const float*)d_in[5];
    const float* bdw    = (const float*)d_in[6];
    const float* gA     = (const float*)d_in[7];
    const float* gB     = (const float*)d_in[8];
    const float* uA     = (const float*)d_in[9];
    const float* uB     = (const float*)d_in[10];
    const float* dA     = (const float*)d_in[11];
    const float* dB     = (const float*)d_in[12];
    float* out = (float*)d_out;

    static bool attr_set = false;
    if (!attr_set){
        cudaFuncSetAttribute(gemm_tf32, cudaFuncAttributeMaxDynamicSharedMemorySize, SMEM_BYTES);
        cudaFuncSetAttribute(gateup_kernel, cudaFuncAttributeMaxDynamicSharedMemorySize, GU_SMEM_BYTES);
        cudaFuncSetAttribute(corr_kernel, cudaFuncAttributeMaxDynamicSharedMemorySize, C_SMEM_BYTES);
        attr_set = true;
    }

    float *p_xc, *p_fusedW, *p_baseout, *p_hmixext, *p_dac, *p_bcomb, *p_gBc, *p_uBc;
    cudaGetSymbolAddress((void**)&p_xc,      g_xc);
    cudaGetSymbolAddress((void**)&p_fusedW,  g_fusedW);
    cudaGetSymbolAddress((void**)&p_baseout, g_baseout);
    cudaGetSymbolAddress((void**)&p_hmixext, g_hmixext);
    cudaGetSymbolAddress((void**)&p_dac,     g_dac);
    cudaGetSymbolAddress((void**)&p_bcomb,   g_bcomb);
    cudaGetSymbolAddress((void**)&p_gBc,     g_gBc);
    cudaGetSymbolAddress((void**)&p_uBc,     g_uBc);

    zero_cnt_kernel<<<1, 32>>>();
    routing_kernel<<<NTOK, 256>>>(x, conf_w, conf_b, wealth);
    tilemeta_kernel<<<1, 32>>>();

    launch_conv(x,   p_xc, (size_t)NTOK*HD);
    launch_conv(bgw, p_fusedW,                        (size_t)ID*HD);
    launch_conv(buw, p_fusedW + (size_t)ID*HD,        (size_t)ID*HD);
    launch_conv(gA,  p_fusedW + (size_t)2*ID*HD,      (size_t)EC*HD);
    launch_conv(uA,  p_fusedW + (size_t)(2*ID+EC)*HD, (size_t)EC*HD);
    launch_conv(dA,  p_dac, (size_t)EC*ID);
    launch_conv(gB,  p_gBc, (size_t)NE*ID*NR);
    launch_conv(uB,  p_uBc, (size_t)NE*ID*NR);
    bcomb_kernel<<<((size_t)HD*KDOWN)/256, 256>>>(bdw, dB);

    // fused x-side GEMM; round tg/tu output columns (>= 2*ID) to tf32
    launch_gemm(p_xc, p_fusedW, p_baseout, NTOK, NF, HD, HD, HD, 2*ID);

    // fused grouped gate/up (cp.async, pre-rounded operands)
    gateup_kernel<<<dim3(ID/128, MAXTILE), 256, GU_SMEM_BYTES>>>();

    // hmix head
    addhead_kernel<<<(NTOK*ID/4)/256, 256>>>();

    // grouped down-LoRA correction, split-K 4
    corr_kernel<<<dim3(4, MAXTILE), 128, C_SMEM_BYTES>>>();
    cvec_kernel<<<(NTOK*EC)/256, 256>>>();

    // fused down projection (no output rounding)
    launch_gemm(p_hmixext, p_bcomb, out, NTOK, HD, KDOWN, KDOWN, KDOWN, 1<<30);
}

// round 12
// speedup vs baseline: 4.5484x; 1.0182x over previous
#include <cuda_runtime.h>
#include <cstdint>
#include <math.h>

#define NTOK 2048
#define HD   2048
#define ID   7168
#define NE   8
#define NR   64
#define EC   (NE*NR)       // 512
#define KDOWN (ID+EC)      // 7680
#define NF   (2*ID+2*EC)   // 15360
#define SCALE 0.25f
#define NSLOT (2*NTOK)     // 4096
#define MAXTILE 40

// main GEMM tiling: 128x128x32, 3 stages, 128 threads (4 warps, 2x2 of 64x64)
#define BM 128
#define BN 128
#define STAGES 3
#define STAGE_FLOATS 8192
#define STAGE_BYTES  32768
#define SMEM_BYTES   (STAGES*STAGE_BYTES)

// gateup v2: 4 matrices x (2 chunks x 128 x 32 floats) = 128KB
#define GU_MATF 8192
#define GU_SMEM_BYTES (4*GU_MATF*4)

// corr kernel: 128x64x32, 3 stages
#define CK 1792
#define C_STAGE_FLOATS 6144
#define C_STAGE_BYTES 24576
#define C_SMEM_BYTES (3*C_STAGE_BYTES)

// ---------------- scratch ----------------
__device__ float g_xc     [(size_t)NTOK*HD];
__device__ float g_fusedW [(size_t)NF*HD];
__device__ float g_baseout[(size_t)NTOK*NF];
__device__ float g_hs     [(size_t)NSLOT*ID];
__device__ float g_hmixext[(size_t)NTOK*KDOWN];
__device__ float g_corrp  [(size_t)4*NSLOT*NR];
__device__ float g_bcomb  [(size_t)HD*KDOWN];
__device__ float g_dac    [(size_t)EC*ID];
__device__ float g_gBc    [(size_t)NE*ID*NR];
__device__ float g_uBc    [(size_t)NE*ID*NR];
__device__ int   g_eids   [NSLOT];
__device__ float g_wts    [NSLOT];
__device__ int   g_cnt    [NE];
__device__ int   g_list   [NE*NSLOT];
__device__ int   g_tile_e [MAXTILE+8];
__device__ int   g_tile_base[MAXTILE+8];
__device__ int   g_ntiles;

// ---------------- helpers ----------------
__device__ __forceinline__ float f2tf32f(float x){
    uint32_t r;
    asm("cvt.rna.tf32.f32 %0, %1;" : "=r"(r) : "f"(x));
    return __uint_as_float(r);
}
__device__ __forceinline__ void mma_tf32(float* c, const uint32_t* a, const uint32_t* b){
    asm volatile(
        "mma.sync.aligned.m16n8k8.row.col.f32.tf32.tf32.f32 "
        "{%0,%1,%2,%3}, {%4,%5,%6,%7}, {%8,%9}, {%0,%1,%2,%3};"
        : "+f"(c[0]), "+f"(c[1]), "+f"(c[2]), "+f"(c[3])
        : "r"(a[0]), "r"(a[1]), "r"(a[2]), "r"(a[3]), "r"(b[0]), "r"(b[1]));
}
__device__ __forceinline__ void cp16(uint32_t smaddr, const void* g){
    asm volatile("cp.async.cg.shared.global [%0], [%1], 16;" :: "r"(smaddr), "l"(g));
}
__device__ __forceinline__ void cp16z(uint32_t smaddr, const void* g, uint32_t bytes){
    asm volatile("cp.async.cg.shared.global [%0], [%1], 16, %2;"
                 :: "r"(smaddr), "l"(g), "r"(bytes));
}
__device__ __forceinline__ void cp_commit(){
    asm volatile("cp.async.commit_group;" ::: "memory");
}
template<int N> __device__ __forceinline__ void cp_wait(){
    asm volatile("cp.async.wait_group %0;" :: "n"(N) : "memory");
}

// ---------------- main tf32 GEMM: C[M,N] = A[M,K]*B[N,K]^T ----------------
__global__ __launch_bounds__(128, 2) void gemm_tf32(
        const float* __restrict__ A, const float* __restrict__ B,
        float* __restrict__ C, int M, int N, int K, int lda, int ldb, int roundN){
    extern __shared__ float sm[];
    const int tid = threadIdx.x;
    const int wid = tid >> 5, lane = tid & 31;
    const int wm = wid >> 1, wn = wid & 1;
    const int grp = lane >> 2, tig = lane & 3;
    const int m0 = blockIdx.y * BM, n0 = blockIdx.x * BN;
    uint32_t smem_base = (uint32_t)__cvta_generic_to_shared(sm);

    const int rA = tid >> 3;
    const int cc = (tid & 7) << 2;
    const uint32_t ccs = (uint32_t)cc ^ (((uint32_t)(rA & 7)) << 2);
    const float* Agp = A + (size_t)(m0 + rA) * lda + cc;
    const float* Bgp = B + (size_t)(n0 + rA) * ldb + cc;
    const size_t rstepA = (size_t)16 * lda;
    const size_t rstepB = (size_t)16 * ldb;

    uint32_t dstA[8], dstB[8];
    #pragma unroll
    for (int q = 0; q < 8; q++){
        dstA[q] = ((uint32_t)(rA + 16*q) * 32u + ccs) * 4u;
        dstB[q] = 16384u + dstA[q];
    }
    const int nch = K >> 5;

    #pragma unroll
    for (int s = 0; s < STAGES-1; s++){
        if (s < nch){
            uint32_t base = smem_base + (uint32_t)s * STAGE_BYTES;
            const float* ag = Agp + (s << 5);
            const float* bg = Bgp + (s << 5);
            #pragma unroll
            for (int q = 0; q < 8; q++) cp16(base + dstA[q], ag + rstepA * q);
            #pragma unroll
            for (int q = 0; q < 8; q++) cp16(base + dstB[q], bg + rstepB * q);
        }
        cp_commit();
    }

    const uint32_t gx = (uint32_t)grp << 2;
    uint32_t aRow[4], bRow[8];
    #pragma unroll
    for (int i = 0; i < 4; i++) aRow[i] = (uint32_t)(wm*64 + i*16 + grp) * 32u;
    #pragma unroll
    for (int j = 0; j < 8; j++) bRow[j] = 4096u + (uint32_t)(wn*64 + j*8 + grp) * 32u;

    float acc[4][8][4];
    #pragma unroll
    for (int i = 0; i < 4; i++)
        #pragma unroll
        for (int j = 0; j < 8; j++)
            #pragma unroll
            for (int q = 0; q < 4; q++) acc[i][j][q] = 0.f;

    for (int c = 0; c < nch; c++){
        cp_wait<STAGES-2>();
        __syncthreads();
        if (c + STAGES-1 < nch){
            const int cn = c + STAGES-1;
            uint32_t base = smem_base + (uint32_t)(cn % STAGES) * STAGE_BYTES;
            const float* ag = Agp + (cn << 5);
            const float* bg = Bgp + (cn << 5);
            #pragma unroll
            for (int q = 0; q < 8; q++) cp16(base + dstA[q], ag + rstepA * q);
            #pragma unroll
            for (int q = 0; q < 8; q++) cp16(base + dstB[q], bg + rstepB * q);
        }
        cp_commit();

        const uint32_t* st = (const uint32_t*)(sm + (size_t)(c % STAGES) * STAGE_FLOATS);
        #pragma unroll
        for (int kk = 0; kk < 4; kk++){
            const uint32_t k0 = ((uint32_t)(kk*8) + tig) ^ gx;
            const uint32_t k1 = ((uint32_t)(kk*8) + tig + 4u) ^ gx;
            uint32_t af[4][4], bf[8][2];
            #pragma unroll
            for (int i = 0; i < 4; i++){
                af[i][0] = st[aRow[i] + k0];
                af[i][1] = st[aRow[i] + 256u + k0];
                af[i][2] = st[aRow[i] + k1];
                af[i][3] = st[aRow[i] + 256u + k1];
            }
            #pragma unroll
            for (int j = 0; j < 8; j++){
                bf[j][0] = st[bRow[j] + k0];
                bf[j][1] = st[bRow[j] + k1];
            }
            #pragma unroll
            for (int i = 0; i < 4; i++)
                #pragma unroll
                for (int j = 0; j < 8; j++)
                    mma_tf32(acc[i][j], af[i], bf[j]);
        }
    }

    #pragma unroll
    for (int i = 0; i < 4; i++){
        int r0 = m0 + wm*64 + i*16 + grp;
        float* cr0 = C + (size_t)r0 * N;
        float* cr1 = C + (size_t)(r0 + 8) * N;
        #pragma unroll
        for (int j = 0; j < 8; j++){
            int col = n0 + wn*64 + j*8 + (tig << 1);
            float v0 = acc[i][j][0], v1 = acc[i][j][1];
            float v2 = acc[i][j][2], v3 = acc[i][j][3];
            if (col >= roundN){
                v0 = f2tf32f(v0); v1 = f2tf32f(v1);
                v2 = f2tf32f(v2); v3 = f2tf32f(v3);
            }
            *(float2*)(cr0 + col) = make_float2(v0, v1);
            *(float2*)(cr1 + col) = make_float2(v2, v3);
        }
    }
}

// ---------------- conv ----------------
__global__ void conv_kernel(const float* __restrict__ in, float* __restrict__ out){
    size_t i4 = ((size_t)blockIdx.x * 256 + threadIdx.x) << 2;
    float4 v = *(const float4*)(in + i4);
    v.x = f2tf32f(v.x); v.y = f2tf32f(v.y); v.z = f2tf32f(v.z); v.w = f2tf32f(v.w);
    *(float4*)(out + i4) = v;
}

// ---------------- routing + scatter ----------------
__global__ void zero_cnt_kernel(){ if (threadIdx.x < NE) g_cnt[threadIdx.x] = 0; }

__global__ void routing_kernel(const float* __restrict__ x,
                               const float* __restrict__ cw,
                               const float* __restrict__ cb,
                               const float* __restrict__ wealth){
    int t = blockIdx.x;
    int w = threadIdx.x >> 5, lane = threadIdx.x & 31;
    const float* xr = x + (size_t)t * HD;
    const float* cr = cw + (size_t)w * HD;
    float s = 0.f;
    for (int j = lane; j < HD; j += 32) s += xr[j] * cr[j];
    #pragma unroll
    for (int o = 16; o; o >>= 1) s += __shfl_down_sync(0xffffffffu, s, o);
    __shared__ float bids[NE];
    if (lane == 0){
        float conf = 1.f / (1.f + expf(-(s + cb[w])));
        bids[w] = conf * wealth[w];
    }
    __syncthreads();
    if (threadIdx.x == 0){
        int e0 = 0; float b0 = bids[0];
        for (int e = 1; e < NE; e++) if (bids[e] > b0){ b0 = bids[e]; e0 = e; }
        int e1 = -1; float b1 = -1e30f;
        for (int e = 0; e < NE; e++) if (e != e0 && bids[e] > b1){ b1 = bids[e]; e1 = e; }
        float ed = expf(b1 - b0);
        float inv = 1.f / (1.f + ed);
        g_eids[2*t] = e0; g_eids[2*t+1] = e1;
        g_wts [2*t] = inv; g_wts [2*t+1] = ed * inv;
        int p0 = atomicAdd(&g_cnt[e0], 1); g_list[e0*NSLOT + p0] = 2*t;
        int p1 = atomicAdd(&g_cnt[e1], 1); g_list[e1*NSLOT + p1] = 2*t + 1;
    }
}

__global__ void tilemeta_kernel(){
    if (threadIdx.x == 0){
        int nt = 0;
        for (int e = 0; e < NE; e++){
            int c = g_cnt[e];
            for (int b = 0; b < c; b += 128){
                g_tile_e[nt] = e; g_tile_base[nt] = b; nt++;
            }
        }
        g_ntiles = nt;
    }
}

// ---------------- gateup v2 ----------------
__global__ __launch_bounds__(256, 1) void gateup_kernel(){
    int tileid = blockIdx.y;
    if (tileid >= g_ntiles) return;
    const int e = g_tile_e[tileid];
    const int tbase = g_tile_base[tileid];
    const int cnt = g_cnt[e];
    const int i0 = blockIdx.x << 7;
    extern __shared__ float sm[];
    __shared__ int s_ent[128];
    const int tid = threadIdx.x;
    if (tid < 128){
        int j = tbase + tid;
        s_ent[tid] = (j < cnt) ? g_list[e*NSLOT + j] : -1;
    }
    __syncthreads();
    uint32_t smem_base = (uint32_t)__cvta_generic_to_shared(sm);

    {
        const int rA = tid >> 3;
        const int cc = (tid & 7) << 2;
        const uint32_t ccs = (uint32_t)cc ^ (((uint32_t)(rA & 7)) << 2);
        #pragma unroll
        for (int q = 0; q < 4; q++){
            const int row = rA + 32*q;
            const int ent = s_ent[row];
            const int t = ent >> 1;
            const uint32_t abytes = (ent >= 0) ? 16u : 0u;
            const float* asrc = (ent >= 0)
                ? (g_baseout + (size_t)t*NF + 2*ID + e*NR)
                : g_baseout;
            const float* bsrcg = g_gBc + ((size_t)e*ID + i0 + row)*NR;
            const float* bsrcu = g_uBc + ((size_t)e*ID + i0 + row)*NR;
            #pragma unroll
            for (int ch = 0; ch < 2; ch++){
                const uint32_t dst = ((uint32_t)ch*4096u + (uint32_t)row*32u + ccs)*4u;
                const int kof = ch*32 + cc;
                cp16z(smem_base + dst,                 asrc + kof,      abytes);
                cp16z(smem_base + 32768u + dst,        asrc + EC + kof, abytes);
                cp16 (smem_base + 65536u + dst,        bsrcg + kof);
                cp16 (smem_base + 98304u + dst,        bsrcu + kof);
            }
        }
        cp_commit();
    }
    cp_wait<0>();
    __syncthreads();

    const int wid = tid >> 5, lane = tid & 31;
    const int wm = wid >> 2, wn = wid & 3;
    const int grp = lane >> 2, tig = lane & 3;
    const uint32_t gx = (uint32_t)grp << 2;
    const uint32_t* uAg = (const uint32_t*)sm;
    const uint32_t* uAu = (const uint32_t*)(sm + GU_MATF);
    const uint32_t* uBg = (const uint32_t*)(sm + 2*GU_MATF);
    const uint32_t* uBu = (const uint32_t*)(sm + 3*GU_MATF);

    uint32_t aRow[4], bRow[4];
    #pragma unroll
    for (int i = 0; i < 4; i++) aRow[i] = (uint32_t)(wm*64 + i*16 + grp) * 32u;
    #pragma unroll
    for (int j = 0; j < 4; j++) bRow[j] = (uint32_t)(wn*32 + j*8 + grp) * 32u;

    float accg[4][4][4], accu[4][4][4];
    #pragma unroll
    for (int i = 0; i < 4; i++)
        #pragma unroll
        for (int j = 0; j < 4; j++)
            #pragma unroll
            for (int q = 0; q < 4; q++){ accg[i][j][q]=0.f; accu[i][j][q]=0.f; }

    #pragma unroll
    for (int ch = 0; ch < 2; ch++){
        const uint32_t cb = (uint32_t)ch * 4096u;
        #pragma unroll
        for (int kk = 0; kk < 4; kk++){
            const uint32_t k0 = ((uint32_t)(kk*8) + tig) ^ gx;
            const uint32_t k1 = ((uint32_t)(kk*8) + tig + 4u) ^ gx;
            uint32_t ag[4][4], au[4][4], bg[4][2], bu[4][2];
            #pragma unroll
            for (int i = 0; i < 4; i++){
                ag[i][0] = uAg[cb + aRow[i] + k0];
                ag[i][1] = uAg[cb + aRow[i] + 256u + k0];
                ag[i][2] = uAg[cb + aRow[i] + k1];
                ag[i][3] = uAg[cb + aRow[i] + 256u + k1];
                au[i][0] = uAu[cb + aRow[i] + k0];
                au[i][1] = uAu[cb + aRow[i] + 256u + k0];
                au[i][2] = uAu[cb + aRow[i] + k1];
                au[i][3] = uAu[cb + aRow[i] + 256u + k1];
            }
            #pragma unroll
            for (int j = 0; j < 4; j++){
                bg[j][0] = uBg[cb + bRow[j] + k0];
                bg[j][1] = uBg[cb + bRow[j] + k1];
                bu[j][0] = uBu[cb + bRow[j] + k0];
                bu[j][1] = uBu[cb + bRow[j] + k1];
            }
            #pragma unroll
            for (int i = 0; i < 4; i++)
                #pragma unroll
                for (int j = 0; j < 4; j++){
                    mma_tf32(accg[i][j], ag[i], bg[j]);
                    mma_tf32(accu[i][j], au[i], bu[j]);
                }
        }
    }

    #pragma unroll
    for (int i = 0; i < 4; i++){
        #pragma unroll
        for (int half = 0; half < 2; half++){
            int r = wm*64 + i*16 + grp + half*8;
            int ent = s_ent[r];
            if (ent < 0) continue;
            int t = ent >> 1;
            float w = g_wts[ent];
            const float* brow = g_baseout + (size_t)t*NF;
            float* hrow = g_hs + (size_t)ent*ID;
            #pragma unroll
            for (int j = 0; j < 4; j++){
                int col = i0 + wn*32 + j*8 + (tig << 1);
                float2 bg2 = *(const float2*)(brow + col);
                float2 bu2 = *(const float2*)(brow + ID + col);
                float cg0 = accg[i][j][half*2+0], cg1 = accg[i][j][half*2+1];
                float cu0 = accu[i][j][half*2+0], cu1 = accu[i][j][half*2+1];
                float gate0 = bg2.x + SCALE*cg0, gate1 = bg2.y + SCALE*cg1;
                float up0 = bu2.x + SCALE*cu0,  up1 = bu2.y + SCALE*cu1;
                float h0 = gate0 * (1.f/(1.f+__expf(-gate0))) * up0;
                float h1 = gate1 * (1.f/(1.f+__expf(-gate1))) * up1;
                *(float2*)(hrow + col) = make_float2(f2tf32f(w*h0), f2tf32f(w*h1));
            }
        }
    }
}

// ---------------- grouped corr GEMM ----------------
__global__ __launch_bounds__(128, 2) void corr_kernel(){
    int tileid = blockIdx.y;
    if (tileid >= g_ntiles) return;
    const int e = g_tile_e[tileid];
    const int tbase = g_tile_base[tileid];
    const int cnt = g_cnt[e];
    const int ks = blockIdx.x;
    extern __shared__ float sm[];
    __shared__ int s_ent[128];
    const int tid = threadIdx.x;
    if (tid < 128){
        int j = tbase + tid;
        s_ent[tid] = (j < cnt) ? g_list[e*NSLOT + j] : -1;
    }
    __syncthreads();
    uint32_t smem_base = (uint32_t)__cvta_generic_to_shared(sm);

    const int rA = tid >> 3;
    const int cc = (tid & 7) << 2;
    const uint32_t ccs = (uint32_t)cc ^ (((uint32_t)(rA & 7)) << 2);
    const size_t koff0 = (size_t)ks*CK + cc;

    const float* Asrc[8]; uint32_t Abytes[8];
    #pragma unroll
    for (int q = 0; q < 8; q++){
        int ent = s_ent[rA + 16*q];
        Asrc[q] = (ent >= 0) ? (g_hs + (size_t)ent*ID + koff0) : g_hs;
        Abytes[q] = (ent >= 0) ? 16u : 0u;
    }
    const float* Bsrc[4];
    #pragma unroll
    for (int q = 0; q < 4; q++)
        Bsrc[q] = g_dac + (size_t)(e*NR + rA + 16*q)*ID + koff0;

    uint32_t dstA[8], dstB[4];
    #pragma unroll
    for (int q = 0; q < 8; q++) dstA[q] = ((uint32_t)(rA + 16*q) * 32u + ccs) * 4u;
    #pragma unroll
    for (int q = 0; q < 4; q++) dstB[q] = 16384u + ((uint32_t)(rA + 16*q) * 32u + ccs) * 4u;

    const int nch = CK >> 5;

    #pragma unroll
    for (int s = 0; s < 2; s++){
        uint32_t base = smem_base + (uint32_t)s * C_STAGE_BYTES;
        #pragma unroll
        for (int q = 0; q < 8; q++) cp16z(base + dstA[q], Asrc[q] + (s<<5), Abytes[q]);
        #pragma unroll
        for (int q = 0; q < 4; q++) cp16(base + dstB[q], Bsrc[q] + (s<<5));
        cp_commit();
    }

    const int wid = tid >> 5, lane = tid & 31;
    const int wm = wid >> 1, wn = wid & 1;
    const int grp = lane >> 2, tig = lane & 3;
    const uint32_t gx = (uint32_t)grp << 2;
    uint32_t aRow[4], bRow[4];
    #pragma unroll
    for (int i = 0; i < 4; i++) aRow[i] = (uint32_t)(wm*64 + i*16 + grp) * 32u;
    #pragma unroll
    for (int j = 0; j < 4; j++) bRow[j] = 4096u + (uint32_t)(wn*32 + j*8 + grp) * 32u;

    float acc[4][4][4];
    #pragma unroll
    for (int i = 0; i < 4; i++)
        #pragma unroll
        for (int j = 0; j < 4; j++)
            #pragma unroll
            for (int q = 0; q < 4; q++) acc[i][j][q] = 0.f;

    for (int c = 0; c < nch; c++){
        cp_wait<1>();
        __syncthreads();
        if (c + 2 < nch){
            const int cn = c + 2;
            uint32_t base = smem_base + (uint32_t)(cn % 3) * C_STAGE_BYTES;
            #pragma unroll
            for (int q = 0; q < 8; q++) cp16z(base + dstA[q], Asrc[q] + (cn<<5), Abytes[q]);
            #pragma unroll
            for (int q = 0; q < 4; q++) cp16(base + dstB[q], Bsrc[q] + (cn<<5));
        }
        cp_commit();

        const uint32_t* st = (const uint32_t*)(sm + (size_t)(c % 3) * C_STAGE_FLOATS);
        #pragma unroll
        for (int kk = 0; kk < 4; kk++){
            const uint32_t k0 = ((uint32_t)(kk*8) + tig) ^ gx;
            const uint32_t k1 = ((uint32_t)(kk*8) + tig + 4u) ^ gx;
            uint32_t af[4][4], bf[4][2];
            #pragma unroll
            for (int i = 0; i < 4; i++){
                af[i][0] = st[aRow[i] + k0];
                af[i][1] = st[aRow[i] + 256u + k0];
                af[i][2] = st[aRow[i] + k1];
                af[i][3] = st[aRow[i] + 256u + k1];
            }
            #pragma unroll
            for (int j = 0; j < 4; j++){
                bf[j][0] = st[bRow[j] + k0];
                bf[j][1] = st[bRow[j] + k1];
            }
            #pragma unroll
            for (int i = 0; i < 4; i++)
                #pragma unroll
                for (int j = 0; j < 4; j++)
                    mma_tf32(acc[i][j], af[i], bf[j]);
        }
    }

    #pragma unroll
    for (int i = 0; i < 4; i++){
        #pragma unroll
        for (int half = 0; half < 2; half++){
            int r = wm*64 + i*16 + grp + half*8;
            int ent = s_ent[r];
            if (ent < 0) continue;
            float* crow = g_corrp + ((size_t)ks*NSLOT + ent)*NR;
            #pragma unroll
            for (int j = 0; j < 4; j++){
                int col = wn*32 + j*8 + (tig << 1);
                *(float2*)(crow + col) =
                    make_float2(acc[i][j][half*2+0], acc[i][j][half*2+1]);
            }
        }
    }
}

// ---------------- bcomb ----------------
__global__ void bcomb_kernel(const float* __restrict__ bdw, const float* __restrict__ dB){
    size_t idx = (size_t)blockIdx.x * 256 + threadIdx.x;
    int h = (int)(idx / KDOWN); int k = (int)(idx % KDOWN);
    float v;
    if (k < ID) v = bdw[(size_t)h * ID + k];
    else { int j = k - ID; int e = j >> 6; int r = j & 63;
           v = dB[((size_t)e * HD + h) * NR + r]; }
    g_bcomb[idx] = f2tf32f(v);
}

// hmix head: hs0+hs1
__global__ void addhead_kernel(){
    size_t i4 = ((size_t)blockIdx.x * 256 + threadIdx.x) << 2;
    int t = (int)(i4 / ID); int col = (int)(i4 % ID);
    float4 a = *(const float4*)&g_hs[(size_t)(2*t)*ID + col];
    float4 b = *(const float4*)&g_hs[(size_t)(2*t+1)*ID + col];
    float4 o;
    o.x = f2tf32f(a.x+b.x); o.y = f2tf32f(a.y+b.y);
    o.z = f2tf32f(a.z+b.z); o.w = f2tf32f(a.w+b.w);
    *(float4*)&g_hmixext[(size_t)t * KDOWN + col] = o;
}

// cvec tail
__global__ void cvec_kernel(){
    int idx = blockIdx.x * 256 + threadIdx.x;
    int t = idx >> 9, j = idx & 511;
    int e = j >> 6, r = j & 63;
    float v = 0.f;
    #pragma unroll
    for (int k = 0; k < 2; k++){
        int ent = 2*t + k;
        if (g_eids[ent] == e){
            #pragma unroll
            for (int s = 0; s < 4; s++)
                v += g_corrp[((size_t)s*NSLOT + ent)*NR + r];
        }
    }
    g_hmixext[(size_t)t * KDOWN + ID + j] = f2tf32f(SCALE * v);
}

// ---------------- launch ----------------
static void launch_gemm_s(cudaStream_t st, const float* A, const float* B, float* C,
                          int M, int N, int K, int lda, int ldb, int roundN){
    dim3 grid(N / BN, M / BM);
    gemm_tf32<<<grid, 128, SMEM_BYTES, st>>>(A, B, C, M, N, K, lda, ldb, roundN);
}
static void launch_conv_s(cudaStream_t st, const float* in, float* out, size_t n){
    conv_kernel<<<(unsigned)((n / 4) / 256), 256, 0, st>>>(in, out);
}

extern "C" void kernel_launch(void* const* d_in, const int* in_sizes, int n_in,
                              void* d_out, int out_size){
    const float* x      = (const float*)d_in[0];
    const float* conf_w = (const float*)d_in[1];
    const float* conf_b = (const float*)d_in[2];
    const float* wealth = (const float*)d_in[3];
    const float* bgw    = (const float*)d_in[4];
    const float* buw    = (const float*)d_in[5];
    const float* bdw    = (const float*)d_in[6];
    const float* gA     = (const float*)d_in[7];
    const float* gB     = (const float*)d_in[8];
    const float* uA     = (const float*)d_in[9];
    const float* uB     = (const float*)d_in[10];
    const float* dA     = (const float*)d_in[11];
    const float* dB     = (const float*)d_in[12];
    float* out = (float*)d_out;

    static bool init_done = false;
    static cudaStream_t s1, s2;
    static cudaEvent_t evFork, evS1, evS2, evGate, evAdd;
    if (!init_done){
        cudaFuncSetAttribute(gemm_tf32, cudaFuncAttributeMaxDynamicSharedMemorySize, SMEM_BYTES);
        cudaFuncSetAttribute(gateup_kernel, cudaFuncAttributeMaxDynamicSharedMemorySize, GU_SMEM_BYTES);
        cudaFuncSetAttribute(corr_kernel, cudaFuncAttributeMaxDynamicSharedMemorySize, C_SMEM_BYTES);
        cudaStreamCreateWithFlags(&s1, cudaStreamNonBlocking);
        cudaStreamCreateWithFlags(&s2, cudaStreamNonBlocking);
        cudaEventCreateWithFlags(&evFork, cudaEventDisableTiming);
        cudaEventCreateWithFlags(&evS1,   cudaEventDisableTiming);
        cudaEventCreateWithFlags(&evS2,   cudaEventDisableTiming);
        cudaEventCreateWithFlags(&evGate, cudaEventDisableTiming);
        cudaEventCreateWithFlags(&evAdd,  cudaEventDisableTiming);
        init_done = true;
    }

    float *p_xc, *p_fusedW, *p_baseout, *p_hmixext, *p_dac, *p_bcomb, *p_gBc, *p_uBc;
    cudaGetSymbolAddress((void**)&p_xc,      g_xc);
    cudaGetSymbolAddress((void**)&p_fusedW,  g_fusedW);
    cudaGetSymbolAddress((void**)&p_baseout, g_baseout);
    cudaGetSymbolAddress((void**)&p_hmixext, g_hmixext);
    cudaGetSymbolAddress((void**)&p_dac,     g_dac);
    cudaGetSymbolAddress((void**)&p_bcomb,   g_bcomb);
    cudaGetSymbolAddress((void**)&p_gBc,     g_gBc);
    cudaGetSymbolAddress((void**)&p_uBc,     g_uBc);

    cudaStream_t s0 = 0;   // legacy/default stream (harness captures here)

    // ---- fork s1, s2 off s0 ----
    cudaEventRecord(evFork, s0);
    cudaStreamWaitEvent(s1, evFork, 0);
    cudaStreamWaitEvent(s2, evFork, 0);

    // s0: routing path + x conversion
    zero_cnt_kernel<<<1, 32, 0, s0>>>();
    routing_kernel<<<NTOK, 256, 0, s0>>>(x, conf_w, conf_b, wealth);
    tilemeta_kernel<<<1, 32, 0, s0>>>();
    launch_conv_s(s0, x, p_xc, (size_t)NTOK*HD);

    // s1: fusedW conversions (needed by x-GEMM only)
    launch_conv_s(s1, bgw, p_fusedW,                        (size_t)ID*HD);
    launch_conv_s(s1, buw, p_fusedW + (size_t)ID*HD,        (size_t)ID*HD);
    launch_conv_s(s1, gA,  p_fusedW + (size_t)2*ID*HD,      (size_t)EC*HD);
    launch_conv_s(s1, uA,  p_fusedW + (size_t)(2*ID+EC)*HD, (size_t)EC*HD);
    cudaEventRecord(evS1, s1);

    // s2: gateup/corr/down-proj operand prep (hidden under x-GEMM)
    launch_conv_s(s2, gB, p_gBc, (size_t)NE*ID*NR);
    launch_conv_s(s2, uB, p_uBc, (size_t)NE*ID*NR);
    launch_conv_s(s2, dA, p_dac, (size_t)EC*ID);
    bcomb_kernel<<<((size_t)HD*KDOWN)/256, 256, 0, s2>>>(bdw, dB);
    cudaEventRecord(evS2, s2);

    // x-side fused GEMM (waits for fusedW)
    cudaStreamWaitEvent(s0, evS1, 0);
    launch_gemm_s(s0, p_xc, p_fusedW, p_baseout, NTOK, NF, HD, HD, HD, 2*ID);

    // gateup (needs gBc/uBc from s2)
    cudaStreamWaitEvent(s0, evS2, 0);
    gateup_kernel<<<dim3(ID/128, MAXTILE), 256, GU_SMEM_BYTES, s0>>>();
    cudaEventRecord(evGate, s0);

    // addhead on s1 concurrent with corr on s0
    cudaStreamWaitEvent(s1, evGate, 0);
    addhead_kernel<<<(NTOK*ID/4)/256, 256, 0, s1>>>();
    cudaEventRecord(evAdd, s1);

    corr_kernel<<<dim3(4, MAXTILE), 128, C_SMEM_BYTES, s0>>>();
    cvec_kernel<<<(NTOK*EC)/256, 256, 0, s0>>>();

    // down projection joins addhead
    cudaStreamWaitEvent(s0, evAdd, 0);
    launch_gemm_s(s0, p_hmixext, p_bcomb, out, NTOK, HD, KDOWN, KDOWN, KDOWN, 1<<30);
}